// round 2
// baseline (speedup 1.0000x reference)
#include <cuda_runtime.h>
#include <math.h>

#define BB 2
#define TT 4
#define CIN 128
#define HH 64
#define WW 64
#define DM 256
#define NQ 300
#define NP 8
#define PS 3
#define NL 6
#define HW (HH*WW)          // 4096
#define ROWS (BB*NQ)        // 600
#define RP (BB*NQ*NP)       // 4800
#define KP (PS*PS*DM)       // 2304
#define K3 (3*CIN)          // 384

// ----------------------------- scratch (device globals) -----------------------------
__device__ float g_S[BB*K3*HW];        // temporal sums, (b, kd*128+i, p)
__device__ float g_Wf[DM*K3];          // fused temporal+input-proj weight
__device__ float g_bf[DM];
__device__ float g_x[BB*DM*HW];        // projected + pos
__device__ float g_lat[BB*DM*HW];      // lateral output (channel-first)
__device__ float g_f1[BB*HW*DM];       // conv3x3 output, channel-LAST
__device__ float g_wsm_flat[DM*KP];    // reordered conv weights [o][tap*256+c]
__device__ float g_queries[ROWS*DM];
__device__ float g_boxes[ROWS*4];
__device__ float g_h1[ROWS*DM];
__device__ float g_ref[ROWS*NP*2];
__device__ float g_sampled[RP*KP];
__device__ float g_pv[RP*DM];
__device__ float g_pvm[ROWS*DM];
__device__ float g_kv[ROWS*DM];
__device__ float g_q[ROWS*DM];
__device__ float g_attn[ROWS*NQ];
__device__ float g_att_out[ROWS*DM];
__device__ float g_hb[ROWS*DM];

// ----------------------------- generic tiled fp32 GEMM -----------------------------
// C[z][m][n] = act( alpha * sum_k A[z][m][k] * B(z,k,n) + biasRow[m] + biasCol[n] ) (+ Cres)
// wTrans=1: B(z,k,n) = W[z*sW + n*ldw + k]   (NT, weight matrices [o][k])
// wTrans=0: B(z,k,n) = W[z*sW + k*ldw + n]   (NN, activations [k][n])
template<int BM,int BN,int BK,int TM,int TN>
__global__ void gemm_k(const float* __restrict__ A, const float* __restrict__ W,
                       const float* __restrict__ biasRow, const float* __restrict__ biasCol,
                       const float* __restrict__ Cres, float* __restrict__ C,
                       int M,int N,int K,
                       int lda,int ldw,int ldc,
                       long sA,long sW,long sC,
                       int wTrans,int act,float alpha)
{
    constexpr int THREADS = (BM/TM)*(BN/TN);
    __shared__ float As[BK][BM+4];
    __shared__ float Bs[BK][BN+4];
    int tid = threadIdx.x;
    int tx = tid % (BN/TN);
    int ty = tid / (BN/TN);
    int m0 = blockIdx.y*BM, n0 = blockIdx.x*BN;
    long zA = (long)blockIdx.z*sA, zW=(long)blockIdx.z*sW, zC=(long)blockIdx.z*sC;
    float acc[TM][TN];
    #pragma unroll
    for (int a=0;a<TM;a++)
        #pragma unroll
        for (int b=0;b<TN;b++) acc[a][b]=0.f;

    for (int kk=0; kk<K; kk+=BK){
        for (int e = tid; e < BM*BK; e += THREADS){
            int m = e / BK, k = e % BK;
            int gm = m0+m, gk = kk+k;
            As[k][m] = (gm<M && gk<K) ? A[zA + (long)gm*lda + gk] : 0.f;
        }
        if (wTrans){
            for (int e=tid; e<BN*BK; e+=THREADS){
                int n = e / BK, k = e % BK;
                int gn = n0+n, gk = kk+k;
                Bs[k][n] = (gn<N && gk<K) ? W[zW + (long)gn*ldw + gk] : 0.f;
            }
        } else {
            for (int e=tid; e<BN*BK; e+=THREADS){
                int k = e / BN, n = e % BN;
                int gn = n0+n, gk = kk+k;
                Bs[k][n] = (gn<N && gk<K) ? W[zW + (long)gk*ldw + gn] : 0.f;
            }
        }
        __syncthreads();
        #pragma unroll
        for (int ki=0; ki<BK; ki++){
            float af[TM], bfv[TN];
            #pragma unroll
            for (int a=0;a<TM;a++) af[a] = As[ki][ty*TM+a];
            #pragma unroll
            for (int b=0;b<TN;b++) bfv[b] = Bs[ki][tx*TN+b];
            #pragma unroll
            for (int a=0;a<TM;a++)
                #pragma unroll
                for (int b=0;b<TN;b++)
                    acc[a][b] += af[a]*bfv[b];
        }
        __syncthreads();
    }
    for (int a=0;a<TM;a++){
        int gm = m0 + ty*TM + a;
        if (gm >= M) continue;
        float br = biasRow ? biasRow[gm] : 0.f;
        for (int b=0;b<TN;b++){
            int gn = n0 + tx*TN + b;
            if (gn >= N) continue;
            float v = acc[a][b]*alpha + br + (biasCol ? biasCol[gn] : 0.f);
            if (act==1) v = fmaxf(v, 0.f);
            long idx = zC + (long)gm*ldc + gn;
            if (Cres) v += Cres[idx];
            C[idx] = v;
        }
    }
}

// ----------------------------- small kernels -----------------------------

// Wf[d][kd*128+i] = (1/T) * sum_o w_in[d,o] * w_tf[o,i,kd];  bf[d]=b_in[d]+sum_o w_in[d,o]*b_tf[o]
__global__ void k_fuse_w(const float* __restrict__ w_tf, const float* __restrict__ b_tf,
                         const float* __restrict__ w_in, const float* __restrict__ b_in)
{
    int d = blockIdx.x;
    int t = threadIdx.x;   // 128
    __shared__ float win_s[CIN];
    __shared__ float red[CIN];
    win_s[t] = w_in[d*CIN + t];
    __syncthreads();
    int i = t;
    for (int kd=0; kd<3; kd++){
        float acc = 0.f;
        for (int o=0;o<CIN;o++) acc += win_s[o]*w_tf[(o*CIN + i)*3 + kd];
        g_Wf[d*K3 + kd*CIN + i] = acc * (1.0f/TT);
    }
    red[t] = win_s[t]*b_tf[t];
    __syncthreads();
    for (int s=64;s>0;s>>=1){ if (t<s) red[t]+=red[t+s]; __syncthreads(); }
    if (t==0) g_bf[d] = b_in[d] + red[0];
}

// reorder w_sm[0] (D,D,3,3) -> [o][tap*256 + c]
__global__ void k_wsm_flat(const float* __restrict__ w_sm){
    int idx = blockIdx.x*256 + threadIdx.x;
    if (idx >= DM*KP) return;
    int o = idx / KP;
    int r = idx % KP;
    int t = r / DM, c = r % DM;
    g_wsm_flat[idx] = w_sm[((long)o*DM + c)*9 + t];
}

// temporal sums
__global__ void k_tsum(const float* __restrict__ feat){
    int idx = blockIdx.x*256 + threadIdx.x;
    if (idx >= BB*CIN*HW) return;
    int p = idx % HW;
    int i = (idx/HW) % CIN;
    int b = idx/(HW*CIN);
    const float* f = feat + (((long)b*TT)*CIN + i)*HW + p;
    const long st = (long)CIN*HW;
    float v0=f[0], v1=f[st], v2=f[2*st], v3=f[3*st];
    float s = v0+v1+v2+v3;
    long base = (long)b*K3*HW;
    g_S[base + ((long)(0*CIN+i))*HW + p] = s - v3;   // kernel tap 0: sums t=0..T-2
    g_S[base + ((long)(1*CIN+i))*HW + p] = s;        // tap 1: all t
    g_S[base + ((long)(2*CIN+i))*HW + p] = s - v0;   // tap 2: t=1..T-1
}

// add sine positional encoding to g_x (channel-first)
__global__ void k_addpos(){
    int idx = blockIdx.x*256 + threadIdx.x;
    if (idx >= BB*DM*HW) return;
    int p = idx % HW;
    int d = (idx/HW) % DM;
    int y = p / WW, x2 = p % WW;
    const float two_pi = 6.28318530717958647692f;
    int c2, coord;
    if (d < 128){ c2 = d; coord = y; }
    else        { c2 = d-128; coord = x2; }
    int i = c2 >> 1;
    int par = c2 & 1;
    float cn = (float)(coord+1) / (64.0f + 1e-6f) * two_pi;
    float ex = (float)(2*(i>>1)) / 64.0f;
    float dimt = powf(10000.0f, ex);
    float a = cn / dimt;
    g_x[idx] += par ? cosf(a) : sinf(a);
}

// 3x3 conv (scale 1 only), im2col-style GEMM, output channel-last into g_f1
// grid: (y=64, mtile=2, b=2), block 256.  BM=128 out ch, BN=64 pixels, BK=16
__global__ void k_conv3(const float* __restrict__ bias){
    __shared__ float Ws[16][128+4];
    __shared__ float Xs[16][64+4];
    int tid = threadIdx.x;
    int tx = tid % 16, ty = tid / 16;
    int y  = blockIdx.x;
    int m0 = blockIdx.y*128;
    int b  = blockIdx.z;
    const float* lat = g_lat + (long)b*DM*HW;
    float acc[8][4];
    #pragma unroll
    for (int a=0;a<8;a++)
        #pragma unroll
        for (int c=0;c<4;c++) acc[a][c]=0.f;

    for (int kk=0; kk<KP; kk+=16){
        int t  = kk >> 8;          // tap index (constant over this 16-slice)
        int c0 = kk & 255;
        int dy = t/3 - 1, dx = t%3 - 1;
        int yy = y + dy;
        bool rowok = (yy>=0 && yy<HH);
        for (int e=tid; e<128*16; e+=256){
            int o = e >> 4, k = e & 15;
            Ws[k][o] = g_wsm_flat[(long)(m0+o)*KP + kk + k];
        }
        for (int e=tid; e<16*64; e+=256){
            int k = e >> 6, x = e & 63;
            int xx = x + dx;
            float v = 0.f;
            if (rowok && xx>=0 && xx<WW) v = lat[(long)(c0+k)*HW + yy*WW + xx];
            Xs[k][x] = v;
        }
        __syncthreads();
        #pragma unroll
        for (int ki=0; ki<16; ki++){
            float af[8], bfv[4];
            #pragma unroll
            for (int a=0;a<8;a++) af[a]=Ws[ki][ty*8+a];
            #pragma unroll
            for (int c=0;c<4;c++) bfv[c]=Xs[ki][tx*4+c];
            #pragma unroll
            for (int a=0;a<8;a++)
                #pragma unroll
                for (int c=0;c<4;c++) acc[a][c]+=af[a]*bfv[c];
        }
        __syncthreads();
    }
    for (int c=0;c<4;c++){
        int x = tx*4 + c;
        long base = (((long)b*HH + y)*WW + x)*DM + m0 + ty*8;
        #pragma unroll
        for (int a=0;a<8;a++)
            g_f1[base + a] = acc[a][c] + bias[m0+ty*8+a];
    }
}

__global__ void k_init(const float* __restrict__ q_embed, const float* __restrict__ q_pos,
                       const float* __restrict__ boxes0){
    int idx = blockIdx.x*256 + threadIdx.x;
    if (idx < ROWS*DM){
        int qd = idx % (NQ*DM);
        g_queries[idx] = q_embed[qd] + q_pos[qd];
    }
    if (idx < ROWS*4) g_boxes[idx] = boxes0[idx];
}

// ro = tanh(h1@w_r2^T + b_r2)*0.5; ref = clip(boxes[:,:2]+ro)
__global__ void k_ref(const float* __restrict__ w_r2, const float* __restrict__ b_r2){
    int idx = blockIdx.x*256 + threadIdx.x;
    if (idx >= ROWS*16) return;
    int r = idx >> 4, j = idx & 15;
    const float* h = g_h1 + (long)r*DM;
    const float* wr = w_r2 + j*DM;
    float acc = 0.f;
    for (int k=0;k<DM;k++) acc += h[k]*wr[k];
    float ro = tanhf(acc + b_r2[j]) * 0.5f;
    int c = j & 1;
    float v = g_boxes[r*4 + c] + ro;
    g_ref[idx] = fminf(fmaxf(v, 0.f), 1.f);
}

// bilinear 3x3-patch sampling from channel-last g_f1
__global__ void k_sample(){
    int rp = blockIdx.x;          // 0..RP-1
    int c  = threadIdx.x;         // 0..255
    int b  = rp / (NQ*NP);
    float rx = g_ref[rp*2+0], ry = g_ref[rp*2+1];
    const float* f1 = g_f1 + (long)b*HW*DM;
    float gx0 = rx*2.f - 1.f;
    float gy0 = ry*2.f - 1.f;
    #pragma unroll
    for (int t=0;t<9;t++){
        float ox = (float)(t%3 - 1), oy = (float)(t/3 - 1);
        float gx = gx0 + ox*(2.f/WW);
        float gy = gy0 + oy*(2.f/HH);
        float x = fminf(fmaxf((gx+1.f)*0.5f*(WW-1), 0.f), (float)(WW-1));
        float y = fminf(fmaxf((gy+1.f)*0.5f*(HH-1), 0.f), (float)(HH-1));
        float x0f = floorf(x), y0f = floorf(y);
        float wx = x - x0f, wy = y - y0f;
        int x0 = (int)x0f, y0 = (int)y0f;
        int x1 = min(x0+1, WW-1), y1 = min(y0+1, HH-1);
        const float* p00 = f1 + ((long)y0*WW + x0)*DM;
        const float* p01 = f1 + ((long)y0*WW + x1)*DM;
        const float* p10 = f1 + ((long)y1*WW + x0)*DM;
        const float* p11 = f1 + ((long)y1*WW + x1)*DM;
        float v = p00[c]*(1.f-wx)*(1.f-wy) + p01[c]*wx*(1.f-wy)
                + p10[c]*(1.f-wx)*wy       + p11[c]*wx*wy;
        g_sampled[(long)rp*KP + t*DM + c] = v;
    }
}

__global__ void k_mean_p(){
    int idx = blockIdx.x*256 + threadIdx.x;
    if (idx >= ROWS*DM) return;
    int k = idx % DM;
    long r = idx / DM;
    const float* p = g_pv + r*NP*DM + k;
    float s = 0.f;
    #pragma unroll
    for (int j=0;j<NP;j++) s += p[(long)j*DM];
    g_pvm[idx] = s * (1.0f/NP);
}

__global__ void k_softmax(){
    int r = blockIdx.x;            // 0..599
    float* row = g_attn + (long)r*NQ;
    __shared__ float red[128];
    int t = threadIdx.x;
    float m = -1e30f;
    for (int j=t;j<NQ;j+=128) m = fmaxf(m, row[j]);
    red[t]=m; __syncthreads();
    for (int s=64;s>0;s>>=1){ if (t<s) red[t]=fmaxf(red[t],red[t+s]); __syncthreads(); }
    m = red[0]; __syncthreads();
    float sum=0.f;
    for (int j=t;j<NQ;j+=128){ float e=expf(row[j]-m); row[j]=e; sum+=e; }
    red[t]=sum; __syncthreads();
    for (int s=64;s>0;s>>=1){ if (t<s) red[t]+=red[t+s]; __syncthreads(); }
    float inv = 1.f/red[0];
    for (int j=t;j<NQ;j+=128) row[j]*=inv;
}

__global__ void k_boxupd(const float* __restrict__ w_b2, const float* __restrict__ b_b2){
    int idx = blockIdx.x*256 + threadIdx.x;
    if (idx >= ROWS*4) return;
    int r = idx >> 2, j = idx & 3;
    const float* h = g_hb + (long)r*DM;
    const float* w = w_b2 + j*DM;
    float acc = 0.f;
    for (int k=0;k<DM;k++) acc += h[k]*w[k];
    float delta = 1.f/(1.f + expf(-(acc + b_b2[j])));
    float v = g_boxes[idx] + 0.1f*tanhf(delta - 0.5f);
    g_boxes[idx] = fminf(fmaxf(v, 0.f), 1.f);
}

__global__ void k_final(const float* __restrict__ w_cls, const float* __restrict__ b_cls,
                        float* __restrict__ out){
    int idx = blockIdx.x*256 + threadIdx.x;
    if (idx >= ROWS + ROWS*4) return;
    if (idx < ROWS){
        const float* q = g_queries + (long)idx*DM;
        float acc = 0.f;
        for (int k=0;k<DM;k++) acc += q[k]*w_cls[k];
        out[idx] = acc + b_cls[0];
    } else {
        out[idx] = g_boxes[idx - ROWS];
    }
}

// ----------------------------- launcher -----------------------------
static inline int ceil_div(int a, int b){ return (a+b-1)/b; }

extern "C" void kernel_launch(void* const* d_in, const int* in_sizes, int n_in,
                              void* d_out, int out_size)
{
    const float* feat    = (const float*)d_in[0];
    const float* boxes0  = (const float*)d_in[1];
    const float* w_tf    = (const float*)d_in[2];
    const float* b_tf    = (const float*)d_in[3];
    const float* w_in    = (const float*)d_in[4];
    const float* b_in    = (const float*)d_in[5];
    const float* w_lat   = (const float*)d_in[6];
    const float* b_lat   = (const float*)d_in[7];
    const float* w_sm    = (const float*)d_in[8];
    const float* b_sm    = (const float*)d_in[9];
    const float* q_embed = (const float*)d_in[10];
    const float* q_pos   = (const float*)d_in[11];
    const float* Wq      = (const float*)d_in[12];
    const float* bq      = (const float*)d_in[13];
    const float* Wo      = (const float*)d_in[14];
    const float* bo      = (const float*)d_in[15];
    const float* Wp1     = (const float*)d_in[16];
    const float* bp1     = (const float*)d_in[17];
    const float* Wp2     = (const float*)d_in[18];
    const float* bp2     = (const float*)d_in[19];
    const float* w_r1    = (const float*)d_in[20];
    const float* b_r1    = (const float*)d_in[21];
    const float* w_r2    = (const float*)d_in[22];
    const float* b_r2    = (const float*)d_in[23];
    const float* w_b1    = (const float*)d_in[24];
    const float* b_b1    = (const float*)d_in[25];
    const float* w_b2    = (const float*)d_in[26];
    const float* b_b2    = (const float*)d_in[27];
    const float* w_cls   = (const float*)d_in[28];
    const float* b_cls   = (const float*)d_in[29];
    float* out = (float*)d_out;

    float *pS, *pWf, *pbf, *px, *plat, *pq, *ph1, *psamp, *ppv, *ppvm, *pkv, *pqq, *patt, *pao, *phb;
    cudaGetSymbolAddress((void**)&pS,    g_S);
    cudaGetSymbolAddress((void**)&pWf,   g_Wf);
    cudaGetSymbolAddress((void**)&pbf,   g_bf);
    cudaGetSymbolAddress((void**)&px,    g_x);
    cudaGetSymbolAddress((void**)&plat,  g_lat);
    cudaGetSymbolAddress((void**)&pq,    g_queries);
    cudaGetSymbolAddress((void**)&ph1,   g_h1);
    cudaGetSymbolAddress((void**)&psamp, g_sampled);
    cudaGetSymbolAddress((void**)&ppv,   g_pv);
    cudaGetSymbolAddress((void**)&ppvm,  g_pvm);
    cudaGetSymbolAddress((void**)&pkv,   g_kv);
    cudaGetSymbolAddress((void**)&pqq,   g_q);
    cudaGetSymbolAddress((void**)&patt,  g_attn);
    cudaGetSymbolAddress((void**)&pao,   g_att_out);
    cudaGetSymbolAddress((void**)&phb,   g_hb);

    // ---------------- backbone ----------------
    k_fuse_w<<<DM, CIN>>>(w_tf, b_tf, w_in, b_in);
    k_wsm_flat<<<ceil_div(DM*KP,256), 256>>>(w_sm);
    k_tsum<<<ceil_div(BB*CIN*HW,256), 256>>>(feat);

    // x[b][d][p] = Wf(256x384) @ S[b](384x4096) + bf  (NN)
    gemm_k<128,128,16,8,8><<<dim3(ceil_div(HW,128), ceil_div(DM,128), BB), 256>>>(
        pWf, pS, pbf, nullptr, nullptr, px,
        DM, HW, K3, K3, HW, HW,
        0, (long)K3*HW, (long)DM*HW, 0, 0, 1.0f);
    k_addpos<<<ceil_div(BB*DM*HW,256), 256>>>();

    // lateral (scale 1 only): lat[b][o][p] = w_lat[0] @ x[b] + b_lat[0]
    gemm_k<128,128,16,8,8><<<dim3(ceil_div(HW,128), ceil_div(DM,128), BB), 256>>>(
        w_lat, px, b_lat, nullptr, nullptr, plat,
        DM, HW, DM, DM, HW, HW,
        0, (long)DM*HW, (long)DM*HW, 0, 0, 1.0f);

    // 3x3 conv -> g_f1 channel-last
    k_conv3<<<dim3(HH, 2, BB), 256>>>(b_sm);

    k_init<<<ceil_div(ROWS*DM,256), 256>>>(q_embed, q_pos, boxes0);

    const float inv_sqrt_d = 0.0625f; // 1/sqrt(256)

    // ---------------- decoder ----------------
    for (int l=0; l<NL; l++){
        const float* Wq_l  = Wq  + (long)l*DM*DM;
        const float* bq_l  = bq  + (long)l*DM;
        const float* Wo_l  = Wo  + (long)l*DM*DM;
        const float* bo_l  = bo  + (long)l*DM;
        const float* Wp1_l = Wp1 + (long)l*DM*KP;
        const float* bp1_l = bp1 + (long)l*DM;
        const float* Wp2_l = Wp2 + (long)l*DM*DM;
        const float* bp2_l = bp2 + (long)l*DM;

        // h1 = relu(queries @ w_r1^T + b_r1)
        gemm_k<64,64,16,4,4><<<dim3(ceil_div(DM,64), ceil_div(ROWS,64), 1), 256>>>(
            pq, w_r1, nullptr, b_r1, nullptr, ph1,
            ROWS, DM, DM, DM, DM, DM, 0,0,0, 1, 1, 1.0f);

        k_ref<<<ceil_div(ROWS*16,256), 256>>>(w_r2, b_r2);
        k_sample<<<RP, DM>>>();

        // pv = relu(sampled @ Wp1^T + bp1)   (4800 x 256 x 2304)
        gemm_k<128,128,16,8,8><<<dim3(ceil_div(DM,128), ceil_div(RP,128), 1), 256>>>(
            psamp, Wp1_l, nullptr, bp1_l, nullptr, ppv,
            RP, DM, KP, KP, KP, DM, 0,0,0, 1, 1, 1.0f);

        k_mean_p<<<ceil_div(ROWS*DM,256), 256>>>();

        // kv = pvm @ Wp2^T + bp2
        gemm_k<64,64,16,4,4><<<dim3(ceil_div(DM,64), ceil_div(ROWS,64), 1), 256>>>(
            ppvm, Wp2_l, nullptr, bp2_l, nullptr, pkv,
            ROWS, DM, DM, DM, DM, DM, 0,0,0, 1, 0, 1.0f);

        // q = queries @ Wq^T + bq
        gemm_k<64,64,16,4,4><<<dim3(ceil_div(DM,64), ceil_div(ROWS,64), 1), 256>>>(
            pq, Wq_l, nullptr, bq_l, nullptr, pqq,
            ROWS, DM, DM, DM, DM, DM, 0,0,0, 1, 0, 1.0f);

        // scores[b] = (q[b] @ kv[b]^T) * inv_sqrt_d   (batched)
        gemm_k<64,64,16,4,4><<<dim3(ceil_div(NQ,64), ceil_div(NQ,64), BB), 256>>>(
            pqq, pkv, nullptr, nullptr, nullptr, patt,
            NQ, NQ, DM, DM, DM, NQ,
            (long)NQ*DM, (long)NQ*DM, (long)NQ*NQ, 1, 0, inv_sqrt_d);

        k_softmax<<<ROWS, 128>>>();

        // att_out[b] = attn[b] @ kv[b]  (NN, batched)
        gemm_k<64,64,16,4,4><<<dim3(ceil_div(DM,64), ceil_div(NQ,64), BB), 256>>>(
            patt, pkv, nullptr, nullptr, nullptr, pao,
            NQ, DM, NQ, NQ, DM, DM,
            (long)NQ*NQ, (long)NQ*DM, (long)NQ*DM, 0, 0, 1.0f);

        // queries += att_out @ Wo^T + bo
        gemm_k<64,64,16,4,4><<<dim3(ceil_div(DM,64), ceil_div(ROWS,64), 1), 256>>>(
            pao, Wo_l, nullptr, bo_l, pq, pq,
            ROWS, DM, DM, DM, DM, DM, 0,0,0, 1, 0, 1.0f);

        // hb = relu(queries @ w_b1^T + b_b1)
        gemm_k<64,64,16,4,4><<<dim3(ceil_div(DM,64), ceil_div(ROWS,64), 1), 256>>>(
            pq, w_b1, nullptr, b_b1, nullptr, phb,
            ROWS, DM, DM, DM, DM, DM, 0,0,0, 1, 1, 1.0f);

        k_boxupd<<<ceil_div(ROWS*4,256), 256>>>(w_b2, b_b2);
    }

    // logits + boxes to d_out
    k_final<<<ceil_div(ROWS*5,256), 256>>>(w_cls, b_cls, out);
}

// round 6
// speedup vs baseline: 2.2316x; 2.2316x over previous
#include <cuda_runtime.h>
#include <cuda_bf16.h>
#include <math.h>
#include <stdint.h>

#define BB 2
#define TT 4
#define CIN 128
#define HH 64
#define WW 64
#define DM 256
#define NQ 300
#define NP 8
#define PS 3
#define NL 6
#define HW (HH*WW)          // 4096
#define ROWS (BB*NQ)        // 600
#define RP (BB*NQ*NP)       // 4800
#define KP (PS*PS*DM)       // 2304
#define K3 (3*CIN)          // 384

// ----------------------------- scratch (device globals) -----------------------------
__device__ float g_S[BB*K3*HW];
__device__ float g_Wf[DM*K3];
__device__ float g_bf[DM];
__device__ float g_x[BB*DM*HW];
__device__ float g_lat[BB*DM*HW];
__device__ float g_f1[BB*HW*DM];       // conv3x3 output, channel-LAST
__device__ float g_wsm_flat[DM*KP];
__device__ float g_queries[ROWS*DM];
__device__ float g_boxes[ROWS*4];
__device__ float g_h1[ROWS*DM];
__device__ float g_ref[ROWS*NP*2];
__device__ __nv_bfloat16 g_sampled_bf[RP*KP];     // bf16 sampled features
__device__ __nv_bfloat16 g_Wp1_bf[NL*DM*KP];      // bf16 Wp1 weights
__device__ float g_pv[RP*DM];
__device__ float g_pvm[ROWS*DM];
__device__ float g_kv[ROWS*DM];
__device__ float g_q[ROWS*DM];
__device__ float g_attn[ROWS*NQ];
__device__ float g_att_out[ROWS*DM];
__device__ float g_hb[ROWS*DM];

// ----------------------------- PTX helpers -----------------------------
__device__ __forceinline__ uint32_t smem_u32(const void* p){
    uint32_t a;
    asm("{ .reg .u64 t; cvta.to.shared.u64 t, %1; cvt.u32.u64 %0, t; }" : "=r"(a) : "l"(p));
    return a;
}
__device__ __forceinline__ void cp_async16(uint32_t dst, const void* src){
    asm volatile("cp.async.cg.shared.global [%0], [%1], 16;" :: "r"(dst), "l"(src) : "memory");
}
__device__ __forceinline__ void ldm_x4(uint32_t* r, uint32_t addr){
    asm volatile("ldmatrix.sync.aligned.m8n8.x4.shared.b16 {%0,%1,%2,%3}, [%4];"
                 : "=r"(r[0]), "=r"(r[1]), "=r"(r[2]), "=r"(r[3]) : "r"(addr));
}
__device__ __forceinline__ void mma_bf16(float* c, const uint32_t* a, uint32_t b0, uint32_t b1){
    asm volatile("mma.sync.aligned.m16n8k16.row.col.f32.bf16.bf16.f32 "
                 "{%0,%1,%2,%3}, {%4,%5,%6,%7}, {%8,%9}, {%0,%1,%2,%3};"
                 : "+f"(c[0]), "+f"(c[1]), "+f"(c[2]), "+f"(c[3])
                 : "r"(a[0]), "r"(a[1]), "r"(a[2]), "r"(a[3]), "r"(b0), "r"(b1));
}
#define SWZ(off) ((off) ^ (((off) >> 3) & 0x70))

// ----------------------------- HMMA bf16 GEMM for Wp1 -----------------------------
// pv[rp][o] = relu( sum_k sampled_bf[rp][k] * Wp1_bf[o][k] + bias[o] )
// BM=64, BN=128, BK=64, 8 warps (warp tile 32x32), cp.async double-buffered.
#define WP1_NIT (KP/64)   // 36

__global__ void __launch_bounds__(256) k_wp1_hmma(
    const __nv_bfloat16* __restrict__ A,   // [RP][KP]
    const __nv_bfloat16* __restrict__ Wt,  // [DM][KP]
    const float* __restrict__ bias,        // [DM]
    float* __restrict__ outp)              // [RP][DM]
{
    // smem: A double-buffer 2*8KB, B double-buffer 2*16KB = 48KB
    __shared__ __align__(128) char smem[49152];
    const uint32_t sb = smem_u32(smem);
    const int tid = threadIdx.x;
    const int lane = tid & 31, wid = tid >> 5;
    const int warp_m = wid & 1;       // 2 -> 64 rows
    const int warp_n = wid >> 1;      // 4 -> 128 cols
    const int m0 = blockIdx.x * 64;
    const int n0 = blockIdx.y * 128;

    float acc[2][4][4];
    #pragma unroll
    for (int mi=0;mi<2;mi++)
        #pragma unroll
        for (int ni=0;ni<4;ni++)
            #pragma unroll
            for (int c=0;c<4;c++) acc[mi][ni][c]=0.f;

    // ---- prologue: issue stage 0 ----
    {
        int kk = 0;
        uint32_t abuf = sb;
        uint32_t bbuf = sb + 16384;
        for (int e = tid; e < 512; e += 256){
            int r = e >> 3, c = e & 7;
            uint32_t off = (uint32_t)(r*128 + c*16);
            cp_async16(abuf + SWZ(off), A + (size_t)(m0 + r)*KP + kk + c*8);
        }
        for (int e = tid; e < 1024; e += 256){
            int r = e >> 3, c = e & 7;
            uint32_t off = (uint32_t)(r*128 + c*16);
            cp_async16(bbuf + SWZ(off), Wt + (size_t)(n0 + r)*KP + kk + c*8);
        }
        asm volatile("cp.async.commit_group;" ::: "memory");
    }

    for (int it = 0; it < WP1_NIT; it++){
        if (it + 1 < WP1_NIT){
            int kk = (it + 1) * 64;
            uint32_t abuf = sb + ((it+1)&1)*8192;
            uint32_t bbuf = sb + 16384 + ((it+1)&1)*16384;
            for (int e = tid; e < 512; e += 256){
                int r = e >> 3, c = e & 7;
                uint32_t off = (uint32_t)(r*128 + c*16);
                cp_async16(abuf + SWZ(off), A + (size_t)(m0 + r)*KP + kk + c*8);
            }
            for (int e = tid; e < 1024; e += 256){
                int r = e >> 3, c = e & 7;
                uint32_t off = (uint32_t)(r*128 + c*16);
                cp_async16(bbuf + SWZ(off), Wt + (size_t)(n0 + r)*KP + kk + c*8);
            }
            asm volatile("cp.async.commit_group;" ::: "memory");
            asm volatile("cp.async.wait_group 1;" ::: "memory");
        } else {
            asm volatile("cp.async.wait_group 0;" ::: "memory");
        }
        __syncthreads();

        uint32_t abuf = sb + (it&1)*8192;
        uint32_t bbuf = sb + 16384 + (it&1)*16384;
        #pragma unroll
        for (int ks = 0; ks < 4; ks++){
            uint32_t afr[2][4], bfr[2][4];
            #pragma unroll
            for (int mi = 0; mi < 2; mi++){
                int row = warp_m*32 + mi*16 + (lane & 15);
                uint32_t off = (uint32_t)(row*128 + ks*32 + ((lane>>4)<<4));
                ldm_x4(afr[mi], abuf + SWZ(off));
            }
            #pragma unroll
            for (int p = 0; p < 2; p++){
                int row = warp_n*32 + p*16 + (lane & 15);
                uint32_t off = (uint32_t)(row*128 + ks*32 + ((lane>>4)<<4));
                ldm_x4(bfr[p], bbuf + SWZ(off));
            }
            #pragma unroll
            for (int mi = 0; mi < 2; mi++)
                #pragma unroll
                for (int ni = 0; ni < 4; ni++)
                    mma_bf16(acc[mi][ni], afr[mi],
                             bfr[ni>>1][ni&1], bfr[ni>>1][2 + (ni&1)]);
        }
        __syncthreads();
    }

    // ---- epilogue: bias + relu, fp32 out ----
    #pragma unroll
    for (int ni = 0; ni < 4; ni++){
        int col = n0 + warp_n*32 + ni*8 + (lane & 3)*2;
        float b0 = bias[col], b1 = bias[col+1];
        #pragma unroll
        for (int mi = 0; mi < 2; mi++){
            int r0 = m0 + warp_m*32 + mi*16 + (lane >> 2);
            float2 v0 = make_float2(fmaxf(acc[mi][ni][0] + b0, 0.f),
                                    fmaxf(acc[mi][ni][1] + b1, 0.f));
            float2 v1 = make_float2(fmaxf(acc[mi][ni][2] + b0, 0.f),
                                    fmaxf(acc[mi][ni][3] + b1, 0.f));
            *(float2*)(outp + (size_t)r0*DM + col)     = v0;
            *(float2*)(outp + (size_t)(r0+8)*DM + col) = v1;
        }
    }
}

// ----------------------------- generic tiled fp32 GEMM -----------------------------
template<int BM,int BN,int BK,int TM,int TN>
__global__ void gemm_k(const float* __restrict__ A, const float* __restrict__ W,
                       const float* __restrict__ biasRow, const float* __restrict__ biasCol,
                       const float* __restrict__ Cres, float* __restrict__ C,
                       int M,int N,int K,
                       int lda,int ldw,int ldc,
                       long sA,long sW,long sC,
                       int wTrans,int act,float alpha)
{
    constexpr int THREADS = (BM/TM)*(BN/TN);
    __shared__ float As[BK][BM+4];
    __shared__ float Bs[BK][BN+4];
    int tid = threadIdx.x;
    int tx = tid % (BN/TN);
    int ty = tid / (BN/TN);
    int m0 = blockIdx.y*BM, n0 = blockIdx.x*BN;
    long zA = (long)blockIdx.z*sA, zW=(long)blockIdx.z*sW, zC=(long)blockIdx.z*sC;
    float acc[TM][TN];
    #pragma unroll
    for (int a=0;a<TM;a++)
        #pragma unroll
        for (int b=0;b<TN;b++) acc[a][b]=0.f;

    for (int kk=0; kk<K; kk+=BK){
        for (int e = tid; e < BM*BK; e += THREADS){
            int m = e / BK, k = e % BK;
            int gm = m0+m, gk = kk+k;
            As[k][m] = (gm<M && gk<K) ? A[zA + (long)gm*lda + gk] : 0.f;
        }
        if (wTrans){
            for (int e=tid; e<BN*BK; e+=THREADS){
                int n = e / BK, k = e % BK;
                int gn = n0+n, gk = kk+k;
                Bs[k][n] = (gn<N && gk<K) ? W[zW + (long)gn*ldw + gk] : 0.f;
            }
        } else {
            for (int e=tid; e<BN*BK; e+=THREADS){
                int k = e / BN, n = e % BN;
                int gn = n0+n, gk = kk+k;
                Bs[k][n] = (gn<N && gk<K) ? W[zW + (long)gk*ldw + gn] : 0.f;
            }
        }
        __syncthreads();
        #pragma unroll
        for (int ki=0; ki<BK; ki++){
            float af[TM], bfv[TN];
            #pragma unroll
            for (int a=0;a<TM;a++) af[a] = As[ki][ty*TM+a];
            #pragma unroll
            for (int b=0;b<TN;b++) bfv[b] = Bs[ki][tx*TN+b];
            #pragma unroll
            for (int a=0;a<TM;a++)
                #pragma unroll
                for (int b=0;b<TN;b++)
                    acc[a][b] += af[a]*bfv[b];
        }
        __syncthreads();
    }
    for (int a=0;a<TM;a++){
        int gm = m0 + ty*TM + a;
        if (gm >= M) continue;
        float br = biasRow ? biasRow[gm] : 0.f;
        for (int b=0;b<TN;b++){
            int gn = n0 + tx*TN + b;
            if (gn >= N) continue;
            float v = acc[a][b]*alpha + br + (biasCol ? biasCol[gn] : 0.f);
            if (act==1) v = fmaxf(v, 0.f);
            long idx = zC + (long)gm*ldc + gn;
            if (Cres) v += Cres[idx];
            C[idx] = v;
        }
    }
}

// ----------------------------- small kernels -----------------------------
__global__ void k_fuse_w(const float* __restrict__ w_tf, const float* __restrict__ b_tf,
                         const float* __restrict__ w_in, const float* __restrict__ b_in)
{
    int d = blockIdx.x;
    int t = threadIdx.x;   // 128
    __shared__ float win_s[CIN];
    __shared__ float red[CIN];
    win_s[t] = w_in[d*CIN + t];
    __syncthreads();
    int i = t;
    for (int kd=0; kd<3; kd++){
        float acc = 0.f;
        for (int o=0;o<CIN;o++) acc += win_s[o]*w_tf[(o*CIN + i)*3 + kd];
        g_Wf[d*K3 + kd*CIN + i] = acc * (1.0f/TT);
    }
    red[t] = win_s[t]*b_tf[t];
    __syncthreads();
    for (int s=64;s>0;s>>=1){ if (t<s) red[t]+=red[t+s]; __syncthreads(); }
    if (t==0) g_bf[d] = b_in[d] + red[0];
}

__global__ void k_wsm_flat(const float* __restrict__ w_sm){
    int idx = blockIdx.x*256 + threadIdx.x;
    if (idx >= DM*KP) return;
    int o = idx / KP;
    int r = idx % KP;
    int t = r / DM, c = r % DM;
    g_wsm_flat[idx] = w_sm[((long)o*DM + c)*9 + t];
}

__global__ void k_wp1_cast(const float* __restrict__ Wp1){
    int idx = blockIdx.x*256 + threadIdx.x;
    if (idx >= NL*DM*KP) return;
    g_Wp1_bf[idx] = __float2bfloat16(Wp1[idx]);
}

__global__ void k_tsum(const float* __restrict__ feat){
    int idx = blockIdx.x*256 + threadIdx.x;
    if (idx >= BB*CIN*HW) return;
    int p = idx % HW;
    int i = (idx/HW) % CIN;
    int b = idx/(HW*CIN);
    const float* f = feat + (((long)b*TT)*CIN + i)*HW + p;
    const long st = (long)CIN*HW;
    float v0=f[0], v1=f[st], v2=f[2*st], v3=f[3*st];
    float s = v0+v1+v2+v3;
    long base = (long)b*K3*HW;
    g_S[base + ((long)(0*CIN+i))*HW + p] = s - v3;
    g_S[base + ((long)(1*CIN+i))*HW + p] = s;
    g_S[base + ((long)(2*CIN+i))*HW + p] = s - v0;
}

__global__ void k_addpos(){
    int idx = blockIdx.x*256 + threadIdx.x;
    if (idx >= BB*DM*HW) return;
    int p = idx % HW;
    int d = (idx/HW) % DM;
    int y = p / WW, x2 = p % WW;
    const float two_pi = 6.28318530717958647692f;
    int c2, coord;
    if (d < 128){ c2 = d; coord = y; }
    else        { c2 = d-128; coord = x2; }
    int i = c2 >> 1;
    int par = c2 & 1;
    float cn = (float)(coord+1) / (64.0f + 1e-6f) * two_pi;
    float ex = (float)(2*(i>>1)) / 64.0f;
    float dimt = powf(10000.0f, ex);
    float a = cn / dimt;
    g_x[idx] += par ? cosf(a) : sinf(a);
}

__global__ void k_conv3(const float* __restrict__ bias){
    __shared__ float Ws[16][128+4];
    __shared__ float Xs[16][64+4];
    int tid = threadIdx.x;
    int tx = tid % 16, ty = tid / 16;
    int y  = blockIdx.x;
    int m0 = blockIdx.y*128;
    int b  = blockIdx.z;
    const float* lat = g_lat + (long)b*DM*HW;
    float acc[8][4];
    #pragma unroll
    for (int a=0;a<8;a++)
        #pragma unroll
        for (int c=0;c<4;c++) acc[a][c]=0.f;

    for (int kk=0; kk<KP; kk+=16){
        int t  = kk >> 8;
        int c0 = kk & 255;
        int dy = t/3 - 1, dx = t%3 - 1;
        int yy = y + dy;
        bool rowok = (yy>=0 && yy<HH);
        for (int e=tid; e<128*16; e+=256){
            int o = e >> 4, k = e & 15;
            Ws[k][o] = g_wsm_flat[(long)(m0+o)*KP + kk + k];
        }
        for (int e=tid; e<16*64; e+=256){
            int k = e >> 6, x = e & 63;
            int xx = x + dx;
            float v = 0.f;
            if (rowok && xx>=0 && xx<WW) v = lat[(long)(c0+k)*HW + yy*WW + xx];
            Xs[k][x] = v;
        }
        __syncthreads();
        #pragma unroll
        for (int ki=0; ki<16; ki++){
            float af[8], bfv[4];
            #pragma unroll
            for (int a=0;a<8;a++) af[a]=Ws[ki][ty*8+a];
            #pragma unroll
            for (int c=0;c<4;c++) bfv[c]=Xs[ki][tx*4+c];
            #pragma unroll
            for (int a=0;a<8;a++)
                #pragma unroll
                for (int c=0;c<4;c++) acc[a][c]+=af[a]*bfv[c];
        }
        __syncthreads();
    }
    for (int c=0;c<4;c++){
        int x = tx*4 + c;
        long base = (((long)b*HH + y)*WW + x)*DM + m0 + ty*8;
        #pragma unroll
        for (int a=0;a<8;a++)
            g_f1[base + a] = acc[a][c] + bias[m0+ty*8+a];
    }
}

__global__ void k_init(const float* __restrict__ q_embed, const float* __restrict__ q_pos,
                       const float* __restrict__ boxes0){
    int idx = blockIdx.x*256 + threadIdx.x;
    if (idx < ROWS*DM){
        int qd = idx % (NQ*DM);
        g_queries[idx] = q_embed[qd] + q_pos[qd];
    }
    if (idx < ROWS*4) g_boxes[idx] = boxes0[idx];
}

__global__ void k_ref(const float* __restrict__ w_r2, const float* __restrict__ b_r2){
    int idx = blockIdx.x*256 + threadIdx.x;
    if (idx >= ROWS*16) return;
    int r = idx >> 4, j = idx & 15;
    const float* h = g_h1 + (long)r*DM;
    const float* wr = w_r2 + j*DM;
    float acc = 0.f;
    for (int k=0;k<DM;k++) acc += h[k]*wr[k];
    float ro = tanhf(acc + b_r2[j]) * 0.5f;
    int c = j & 1;
    float v = g_boxes[r*4 + c] + ro;
    g_ref[idx] = fminf(fmaxf(v, 0.f), 1.f);
}

// bilinear 3x3-patch sampling, writes bf16 directly
__global__ void k_sample(){
    int rp = blockIdx.x;
    int c  = threadIdx.x;
    int b  = rp / (NQ*NP);
    float rx = g_ref[rp*2+0], ry = g_ref[rp*2+1];
    const float* f1 = g_f1 + (long)b*HW*DM;
    float gx0 = rx*2.f - 1.f;
    float gy0 = ry*2.f - 1.f;
    #pragma unroll
    for (int t=0;t<9;t++){
        float ox = (float)(t%3 - 1), oy = (float)(t/3 - 1);
        float gx = gx0 + ox*(2.f/WW);
        float gy = gy0 + oy*(2.f/HH);
        float x = fminf(fmaxf((gx+1.f)*0.5f*(WW-1), 0.f), (float)(WW-1));
        float y = fminf(fmaxf((gy+1.f)*0.5f*(HH-1), 0.f), (float)(HH-1));
        float x0f = floorf(x), y0f = floorf(y);
        float wx = x - x0f, wy = y - y0f;
        int x0 = (int)x0f, y0 = (int)y0f;
        int x1 = min(x0+1, WW-1), y1 = min(y0+1, HH-1);
        const float* p00 = f1 + ((long)y0*WW + x0)*DM;
        const float* p01 = f1 + ((long)y0*WW + x1)*DM;
        const float* p10 = f1 + ((long)y1*WW + x0)*DM;
        const float* p11 = f1 + ((long)y1*WW + x1)*DM;
        float v = p00[c]*(1.f-wx)*(1.f-wy) + p01[c]*wx*(1.f-wy)
                + p10[c]*(1.f-wx)*wy       + p11[c]*wx*wy;
        g_sampled_bf[(long)rp*KP + t*DM + c] = __float2bfloat16(v);
    }
}

__global__ void k_mean_p(){
    int idx = blockIdx.x*256 + threadIdx.x;
    if (idx >= ROWS*DM) return;
    int k = idx % DM;
    long r = idx / DM;
    const float* p = g_pv + r*NP*DM + k;
    float s = 0.f;
    #pragma unroll
    for (int j=0;j<NP;j++) s += p[(long)j*DM];
    g_pvm[idx] = s * (1.0f/NP);
}

__global__ void k_softmax(){
    int r = blockIdx.x;
    float* row = g_attn + (long)r*NQ;
    __shared__ float red[128];
    int t = threadIdx.x;
    float m = -1e30f;
    for (int j=t;j<NQ;j+=128) m = fmaxf(m, row[j]);
    red[t]=m; __syncthreads();
    for (int s=64;s>0;s>>=1){ if (t<s) red[t]=fmaxf(red[t],red[t+s]); __syncthreads(); }
    m = red[0]; __syncthreads();
    float sum=0.f;
    for (int j=t;j<NQ;j+=128){ float e=expf(row[j]-m); row[j]=e; sum+=e; }
    red[t]=sum; __syncthreads();
    for (int s=64;s>0;s>>=1){ if (t<s) red[t]+=red[t+s]; __syncthreads(); }
    float inv = 1.f/red[0];
    for (int j=t;j<NQ;j+=128) row[j]*=inv;
}

__global__ void k_boxupd(const float* __restrict__ w_b2, const float* __restrict__ b_b2){
    int idx = blockIdx.x*256 + threadIdx.x;
    if (idx >= ROWS*4) return;
    int r = idx >> 2, j = idx & 3;
    const float* h = g_hb + (long)r*DM;
    const float* w = w_b2 + j*DM;
    float acc = 0.f;
    for (int k=0;k<DM;k++) acc += h[k]*w[k];
    float delta = 1.f/(1.f + expf(-(acc + b_b2[j])));
    float v = g_boxes[idx] + 0.1f*tanhf(delta - 0.5f);
    g_boxes[idx] = fminf(fmaxf(v, 0.f), 1.f);
}

__global__ void k_final(const float* __restrict__ w_cls, const float* __restrict__ b_cls,
                        float* __restrict__ out){
    int idx = blockIdx.x*256 + threadIdx.x;
    if (idx >= ROWS + ROWS*4) return;
    if (idx < ROWS){
        const float* q = g_queries + (long)idx*DM;
        float acc = 0.f;
        for (int k=0;k<DM;k++) acc += q[k]*w_cls[k];
        out[idx] = acc + b_cls[0];
    } else {
        out[idx] = g_boxes[idx - ROWS];
    }
}

// ----------------------------- launcher -----------------------------
static inline int ceil_div(int a, int b){ return (a+b-1)/b; }

extern "C" void kernel_launch(void* const* d_in, const int* in_sizes, int n_in,
                              void* d_out, int out_size)
{
    const float* feat    = (const float*)d_in[0];
    const float* boxes0  = (const float*)d_in[1];
    const float* w_tf    = (const float*)d_in[2];
    const float* b_tf    = (const float*)d_in[3];
    const float* w_in    = (const float*)d_in[4];
    const float* b_in    = (const float*)d_in[5];
    const float* w_lat   = (const float*)d_in[6];
    const float* b_lat   = (const float*)d_in[7];
    const float* w_sm    = (const float*)d_in[8];
    const float* b_sm    = (const float*)d_in[9];
    const float* q_embed = (const float*)d_in[10];
    const float* q_pos   = (const float*)d_in[11];
    const float* Wq      = (const float*)d_in[12];
    const float* bq      = (const float*)d_in[13];
    const float* Wo      = (const float*)d_in[14];
    const float* bo      = (const float*)d_in[15];
    const float* Wp1     = (const float*)d_in[16];
    const float* bp1     = (const float*)d_in[17];
    const float* Wp2     = (const float*)d_in[18];
    const float* bp2     = (const float*)d_in[19];
    const float* w_r1    = (const float*)d_in[20];
    const float* b_r1    = (const float*)d_in[21];
    const float* w_r2    = (const float*)d_in[22];
    const float* b_r2    = (const float*)d_in[23];
    const float* w_b1    = (const float*)d_in[24];
    const float* b_b1    = (const float*)d_in[25];
    const float* w_b2    = (const float*)d_in[26];
    const float* b_b2    = (const float*)d_in[27];
    const float* w_cls   = (const float*)d_in[28];
    const float* b_cls   = (const float*)d_in[29];
    float* out = (float*)d_out;

    float *pS, *pWf, *pbf, *px, *plat, *pq, *ph1, *ppv, *ppvm, *pkv, *pqq, *patt, *pao, *phb;
    __nv_bfloat16 *psamp_bf, *pWp1_bf;
    cudaGetSymbolAddress((void**)&pS,    g_S);
    cudaGetSymbolAddress((void**)&pWf,   g_Wf);
    cudaGetSymbolAddress((void**)&pbf,   g_bf);
    cudaGetSymbolAddress((void**)&px,    g_x);
    cudaGetSymbolAddress((void**)&plat,  g_lat);
    cudaGetSymbolAddress((void**)&pq,    g_queries);
    cudaGetSymbolAddress((void**)&ph1,   g_h1);
    cudaGetSymbolAddress((void**)&psamp_bf, g_sampled_bf);
    cudaGetSymbolAddress((void**)&pWp1_bf,  g_Wp1_bf);
    cudaGetSymbolAddress((void**)&ppv,   g_pv);
    cudaGetSymbolAddress((void**)&ppvm,  g_pvm);
    cudaGetSymbolAddress((void**)&pkv,   g_kv);
    cudaGetSymbolAddress((void**)&pqq,   g_q);
    cudaGetSymbolAddress((void**)&patt,  g_attn);
    cudaGetSymbolAddress((void**)&pao,   g_att_out);
    cudaGetSymbolAddress((void**)&phb,   g_hb);

    // ---------------- backbone ----------------
    k_fuse_w<<<DM, CIN>>>(w_tf, b_tf, w_in, b_in);
    k_wsm_flat<<<ceil_div(DM*KP,256), 256>>>(w_sm);
    k_wp1_cast<<<ceil_div(NL*DM*KP,256), 256>>>(Wp1);
    k_tsum<<<ceil_div(BB*CIN*HW,256), 256>>>(feat);

    gemm_k<128,128,16,8,8><<<dim3(ceil_div(HW,128), ceil_div(DM,128), BB), 256>>>(
        pWf, pS, pbf, nullptr, nullptr, px,
        DM, HW, K3, K3, HW, HW,
        0, (long)K3*HW, (long)DM*HW, 0, 0, 1.0f);
    k_addpos<<<ceil_div(BB*DM*HW,256), 256>>>();

    gemm_k<128,128,16,8,8><<<dim3(ceil_div(HW,128), ceil_div(DM,128), BB), 256>>>(
        w_lat, px, b_lat, nullptr, nullptr, plat,
        DM, HW, DM, DM, HW, HW,
        0, (long)DM*HW, (long)DM*HW, 0, 0, 1.0f);

    k_conv3<<<dim3(HH, 2, BB), 256>>>(b_sm);

    k_init<<<ceil_div(ROWS*DM,256), 256>>>(q_embed, q_pos, boxes0);

    const float inv_sqrt_d = 0.0625f;

    // ---------------- decoder ----------------
    for (int l=0; l<NL; l++){
        const float* Wq_l  = Wq  + (long)l*DM*DM;
        const float* bq_l  = bq  + (long)l*DM;
        const float* Wo_l  = Wo  + (long)l*DM*DM;
        const float* bo_l  = bo  + (long)l*DM;
        const float* bp1_l = bp1 + (long)l*DM;
        const float* Wp2_l = Wp2 + (long)l*DM*DM;
        const float* bp2_l = bp2 + (long)l*DM;

        gemm_k<64,64,16,4,4><<<dim3(ceil_div(DM,64), ceil_div(ROWS,64), 1), 256>>>(
            pq, w_r1, nullptr, b_r1, nullptr, ph1,
            ROWS, DM, DM, DM, DM, DM, 0,0,0, 1, 1, 1.0f);

        k_ref<<<ceil_div(ROWS*16,256), 256>>>(w_r2, b_r2);
        k_sample<<<RP, DM>>>();

        // pv = relu(sampled @ Wp1^T + bp1)  — HMMA bf16
        k_wp1_hmma<<<dim3(RP/64, DM/128), 256>>>(
            psamp_bf, pWp1_bf + (long)l*DM*KP, bp1_l, ppv);

        k_mean_p<<<ceil_div(ROWS*DM,256), 256>>>();

        gemm_k<64,64,16,4,4><<<dim3(ceil_div(DM,64), ceil_div(ROWS,64), 1), 256>>>(
            ppvm, Wp2_l, nullptr, bp2_l, nullptr, pkv,
            ROWS, DM, DM, DM, DM, DM, 0,0,0, 1, 0, 1.0f);

        gemm_k<64,64,16,4,4><<<dim3(ceil_div(DM,64), ceil_div(ROWS,64), 1), 256>>>(
            pq, Wq_l, nullptr, bq_l, nullptr, pqq,
            ROWS, DM, DM, DM, DM, DM, 0,0,0, 1, 0, 1.0f);

        gemm_k<64,64,16,4,4><<<dim3(ceil_div(NQ,64), ceil_div(NQ,64), BB), 256>>>(
            pqq, pkv, nullptr, nullptr, nullptr, patt,
            NQ, NQ, DM, DM, DM, NQ,
            (long)NQ*DM, (long)NQ*DM, (long)NQ*NQ, 1, 0, inv_sqrt_d);

        k_softmax<<<ROWS, 128>>>();

        gemm_k<64,64,16,4,4><<<dim3(ceil_div(DM,64), ceil_div(NQ,64), BB), 256>>>(
            patt, pkv, nullptr, nullptr, nullptr, pao,
            NQ, DM, NQ, NQ, DM, DM,
            (long)NQ*NQ, (long)NQ*DM, (long)NQ*DM, 0, 0, 1.0f);

        gemm_k<64,64,16,4,4><<<dim3(ceil_div(DM,64), ceil_div(ROWS,64), 1), 256>>>(
            pao, Wo_l, nullptr, bo_l, pq, pq,
            ROWS, DM, DM, DM, DM, DM, 0,0,0, 1, 0, 1.0f);

        gemm_k<64,64,16,4,4><<<dim3(ceil_div(DM,64), ceil_div(ROWS,64), 1), 256>>>(
            pq, w_b1, nullptr, b_b1, nullptr, phb,
            ROWS, DM, DM, DM, DM, DM, 0,0,0, 1, 1, 1.0f);

        k_boxupd<<<ceil_div(ROWS*4,256), 256>>>(w_b2, b_b2);
    }

    k_final<<<ceil_div(ROWS*5,256), 256>>>(w_cls, b_cls, out);
}

// round 7
// speedup vs baseline: 6.6767x; 2.9919x over previous
#include <cuda_runtime.h>
#include <cuda_bf16.h>
#include <math.h>
#include <stdint.h>

#define BB 2
#define TT 4
#define CIN 128
#define HH 64
#define WW 64
#define DM 256
#define NQ 300
#define NP 8
#define PS 3
#define NL 6
#define HW (HH*WW)          // 4096
#define ROWS (BB*NQ)        // 600
#define RP (BB*NQ*NP)       // 4800
#define KP (PS*PS*DM)       // 2304
#define K3 (3*CIN)          // 384
#define KQ 320              // padded attn K (300 -> 320)

typedef __nv_bfloat16 bf16;

// ----------------------------- scratch (device globals) -----------------------------
__device__ bf16  g_St[BB*HW*K3];        // temporal sums, channel-last bf16
__device__ bf16  g_Wf_bf[DM*K3];
__device__ float g_bfv[DM];
__device__ float g_xt[BB*HW*DM];        // projected, channel-last fp32 (pre-pos)
__device__ bf16  g_xbf[BB*HW*DM];       // + pos, bf16
__device__ bf16  g_latbf[BB*HW*DM];     // lateral, channel-last bf16
__device__ bf16  g_f1bf[BB*HW*DM];      // conv3x3 out, channel-last bf16
__device__ bf16  g_wsm_bf[DM*KP];
__device__ bf16  g_wlat_bf[DM*DM];
__device__ bf16  g_wr1_bf[DM*DM];
__device__ bf16  g_wb1_bf[DM*DM];
__device__ bf16  g_Wq_bf[NL*DM*DM];
__device__ bf16  g_Wo_bf[NL*DM*DM];
__device__ bf16  g_Wp2_bf[NL*DM*DM];
__device__ bf16  g_Wp1_bf[NL*DM*KP];
__device__ float g_queries[ROWS*DM];
__device__ bf16  g_q_bf[ROWS*DM];
__device__ float g_boxes[ROWS*4];
__device__ float g_h1[ROWS*DM];
__device__ float g_hb[ROWS*DM];
__device__ float g_ref[ROWS*NP*2];
__device__ bf16  g_sampled_bf[RP*KP];
__device__ float g_pv[RP*DM];
__device__ bf16  g_pvm_bf[ROWS*DM];
__device__ bf16  g_kv_bf[ROWS*DM];
__device__ bf16  g_kvt[BB*DM*KQ];       // kv transposed [b][d][q-pad]
__device__ bf16  g_qq_bf[ROWS*DM];
__device__ float g_attn[ROWS*KQ];
__device__ bf16  g_attn_bf[ROWS*KQ];
__device__ bf16  g_ao_bf[ROWS*DM];

// ----------------------------- PTX helpers -----------------------------
__device__ __forceinline__ uint32_t smem_u32(const void* p){
    uint32_t a;
    asm("{ .reg .u64 t; cvta.to.shared.u64 t, %1; cvt.u32.u64 %0, t; }" : "=r"(a) : "l"(p));
    return a;
}
__device__ __forceinline__ void cp_async16z(uint32_t dst, const void* src, uint32_t sz){
    asm volatile("cp.async.cg.shared.global [%0], [%1], 16, %2;" :: "r"(dst), "l"(src), "r"(sz) : "memory");
}
__device__ __forceinline__ void ldm_x4(uint32_t* r, uint32_t addr){
    asm volatile("ldmatrix.sync.aligned.m8n8.x4.shared.b16 {%0,%1,%2,%3}, [%4];"
                 : "=r"(r[0]), "=r"(r[1]), "=r"(r[2]), "=r"(r[3]) : "r"(addr));
}
__device__ __forceinline__ void mma_bf16(float* c, const uint32_t* a, uint32_t b0, uint32_t b1){
    asm volatile("mma.sync.aligned.m16n8k16.row.col.f32.bf16.bf16.f32 "
                 "{%0,%1,%2,%3}, {%4,%5,%6,%7}, {%8,%9}, {%0,%1,%2,%3};"
                 : "+f"(c[0]), "+f"(c[1]), "+f"(c[2]), "+f"(c[3])
                 : "r"(a[0]), "r"(a[1]), "r"(a[2]), "r"(a[3]), "r"(b0), "r"(b1));
}
#define SWZ(off) ((off) ^ (((off) >> 3) & 0x70))

// ===================================================================================
// Generic bf16 HMMA NT GEMM.
// C[z][m][n] = act( alpha * sum_k A[z*sA + m*lda + k] * B[z*sB + n*ldb + k]
//                   + biasN[n] + (Cres ? Cres[idx] : 0) )
// outputs: Cf (fp32), Cb (bf16) at z*sC + m*ldc + n; Ct (bf16 kv-transposed special:
//          b=m/300, q=m%300, index b*DM*KQ + n*KQ + q).
// BM=64, BN=128, BK=64. grid (M/64, N/128, Z). K multiple of 64.
// ===================================================================================
__global__ void __launch_bounds__(256) k_hmma(
    const bf16* __restrict__ A, const bf16* __restrict__ B,
    const float* __restrict__ biasN, const float* __restrict__ Cres,
    float* __restrict__ Cf, bf16* __restrict__ Cb, bf16* __restrict__ Ct,
    int M, int N, int K, int lda, int ldb, int ldc,
    long sA, long sB, long sC,
    int act, float alpha)
{
    __shared__ __align__(128) char smem[49152];
    const uint32_t sb = smem_u32(smem);
    const int tid = threadIdx.x;
    const int lane = tid & 31, wid = tid >> 5;
    const int warp_m = wid & 1;
    const int warp_n = wid >> 1;
    const int m0 = blockIdx.x * 64;
    const int n0 = blockIdx.y * 128;
    const long zo = blockIdx.z;
    const bf16* Ab = A + zo * sA;
    const bf16* Bb = B + zo * sB;
    const int nit = K >> 6;

    float acc[2][4][4];
    #pragma unroll
    for (int mi=0;mi<2;mi++)
        #pragma unroll
        for (int ni=0;ni<4;ni++)
            #pragma unroll
            for (int c=0;c<4;c++) acc[mi][ni][c]=0.f;

    // stage lambda (manual)
    #define STAGE(IT) do { \
        int kk = (IT) * 64; \
        uint32_t abuf = sb + ((IT)&1)*8192; \
        uint32_t bbuf = sb + 16384 + ((IT)&1)*16384; \
        for (int e = tid; e < 512; e += 256){ \
            int r = e >> 3, c = e & 7; \
            int gm = m0 + r; \
            int rm = gm < M ? gm : 0; \
            uint32_t sz = gm < M ? 16u : 0u; \
            uint32_t off = (uint32_t)(r*128 + c*16); \
            cp_async16z(abuf + SWZ(off), Ab + (size_t)rm*lda + kk + c*8, sz); \
        } \
        for (int e = tid; e < 1024; e += 256){ \
            int r = e >> 3, c = e & 7; \
            int gn = n0 + r; \
            int rn = gn < N ? gn : 0; \
            uint32_t sz = gn < N ? 16u : 0u; \
            uint32_t off = (uint32_t)(r*128 + c*16); \
            cp_async16z(bbuf + SWZ(off), Bb + (size_t)rn*ldb + kk + c*8, sz); \
        } \
        asm volatile("cp.async.commit_group;" ::: "memory"); \
    } while(0)

    STAGE(0);
    for (int it = 0; it < nit; it++){
        if (it + 1 < nit){
            STAGE(it+1);
            asm volatile("cp.async.wait_group 1;" ::: "memory");
        } else {
            asm volatile("cp.async.wait_group 0;" ::: "memory");
        }
        __syncthreads();
        uint32_t abuf = sb + (it&1)*8192;
        uint32_t bbuf = sb + 16384 + (it&1)*16384;
        #pragma unroll
        for (int ks = 0; ks < 4; ks++){
            uint32_t afr[2][4], bfr[2][4];
            #pragma unroll
            for (int mi = 0; mi < 2; mi++){
                int row = warp_m*32 + mi*16 + (lane & 15);
                uint32_t off = (uint32_t)(row*128 + ks*32 + ((lane>>4)<<4));
                ldm_x4(afr[mi], abuf + SWZ(off));
            }
            #pragma unroll
            for (int p = 0; p < 2; p++){
                int row = warp_n*32 + p*16 + (lane & 15);
                uint32_t off = (uint32_t)(row*128 + ks*32 + ((lane>>4)<<4));
                ldm_x4(bfr[p], bbuf + SWZ(off));
            }
            #pragma unroll
            for (int mi = 0; mi < 2; mi++)
                #pragma unroll
                for (int ni = 0; ni < 4; ni++)
                    mma_bf16(acc[mi][ni], afr[mi],
                             bfr[ni>>1][ni&1], bfr[ni>>1][2 + (ni&1)]);
        }
        __syncthreads();
    }
    #undef STAGE

    // ---- epilogue ----
    #pragma unroll
    for (int ni = 0; ni < 4; ni++){
        int col = n0 + warp_n*32 + ni*8 + (lane & 3)*2;
        bool cok = col < N;
        float b0 = (cok && biasN) ? biasN[col]   : 0.f;
        float b1 = (cok && biasN) ? biasN[col+1] : 0.f;
        #pragma unroll
        for (int mi = 0; mi < 2; mi++){
            int rbase = m0 + warp_m*32 + mi*16 + (lane >> 2);
            #pragma unroll
            for (int h = 0; h < 2; h++){
                int row = rbase + h*8;
                if (row >= M || !cok) continue;
                float v0 = acc[mi][ni][h*2+0]*alpha + b0;
                float v1 = acc[mi][ni][h*2+1]*alpha + b1;
                long ci = zo*sC + (long)row*ldc + col;
                if (Cres){ v0 += Cres[ci]; v1 += Cres[ci+1]; }
                if (act){ v0 = fmaxf(v0, 0.f); v1 = fmaxf(v1, 0.f); }
                if (Cf){ Cf[ci] = v0; Cf[ci+1] = v1; }
                if (Cb){ Cb[ci] = __float2bfloat16(v0); Cb[ci+1] = __float2bfloat16(v1); }
                if (Ct){
                    int bq = row / NQ, q = row % NQ;
                    long t0 = (long)bq*DM*KQ + (long)col*KQ + q;
                    Ct[t0]      = __float2bfloat16(v0);
                    Ct[t0 + KQ] = __float2bfloat16(v1);
                }
            }
        }
    }
}

// ===================================================================================
// conv3x3 as im2col HMMA: f1[p][o] = sum_{tap,c} lat[p+off(tap)][c] * wsm[o][tap*256+c] + bias[o]
// M = BB*HW (block = one image row: b,y fixed, x=0..63), N=256, K=2304.
// ===================================================================================
__global__ void __launch_bounds__(256) k_conv_hmma(
    const bf16* __restrict__ latbf, const bf16* __restrict__ Wt,
    const float* __restrict__ biasN, bf16* __restrict__ outbf)
{
    __shared__ __align__(128) char smem[49152];
    const uint32_t sb = smem_u32(smem);
    const int tid = threadIdx.x;
    const int lane = tid & 31, wid = tid >> 5;
    const int warp_m = wid & 1;
    const int warp_n = wid >> 1;
    const int m0 = blockIdx.x * 64;
    const int n0 = blockIdx.y * 128;
    const int bimg = m0 >> 12;
    const int yimg = (m0 >> 6) & 63;
    const int nit = KP >> 6;   // 36

    float acc[2][4][4];
    #pragma unroll
    for (int mi=0;mi<2;mi++)
        #pragma unroll
        for (int ni=0;ni<4;ni++)
            #pragma unroll
            for (int c=0;c<4;c++) acc[mi][ni][c]=0.f;

    #define CSTAGE(IT) do { \
        int kk = (IT) * 64; \
        int tap = kk >> 8; \
        int kc  = kk & 255; \
        int dy = tap/3 - 1, dx = tap%3 - 1; \
        int yy = yimg + dy; \
        uint32_t abuf = sb + ((IT)&1)*8192; \
        uint32_t bbuf = sb + 16384 + ((IT)&1)*16384; \
        for (int e = tid; e < 512; e += 256){ \
            int r = e >> 3, c = e & 7; \
            int xx = r + dx; \
            bool ok = (yy >= 0 && yy < HH && xx >= 0 && xx < WW); \
            int pix = bimg*HW + (ok ? (yy*WW + xx) : 0); \
            uint32_t sz = ok ? 16u : 0u; \
            uint32_t off = (uint32_t)(r*128 + c*16); \
            cp_async16z(abuf + SWZ(off), latbf + (size_t)pix*DM + kc + c*8, sz); \
        } \
        for (int e = tid; e < 1024; e += 256){ \
            int r = e >> 3, c = e & 7; \
            uint32_t off = (uint32_t)(r*128 + c*16); \
            cp_async16z(bbuf + SWZ(off), Wt + (size_t)(n0+r)*KP + kk + c*8, 16u); \
        } \
        asm volatile("cp.async.commit_group;" ::: "memory"); \
    } while(0)

    CSTAGE(0);
    for (int it = 0; it < nit; it++){
        if (it + 1 < nit){
            CSTAGE(it+1);
            asm volatile("cp.async.wait_group 1;" ::: "memory");
        } else {
            asm volatile("cp.async.wait_group 0;" ::: "memory");
        }
        __syncthreads();
        uint32_t abuf = sb + (it&1)*8192;
        uint32_t bbuf = sb + 16384 + (it&1)*16384;
        #pragma unroll
        for (int ks = 0; ks < 4; ks++){
            uint32_t afr[2][4], bfr[2][4];
            #pragma unroll
            for (int mi = 0; mi < 2; mi++){
                int row = warp_m*32 + mi*16 + (lane & 15);
                uint32_t off = (uint32_t)(row*128 + ks*32 + ((lane>>4)<<4));
                ldm_x4(afr[mi], abuf + SWZ(off));
            }
            #pragma unroll
            for (int p = 0; p < 2; p++){
                int row = warp_n*32 + p*16 + (lane & 15);
                uint32_t off = (uint32_t)(row*128 + ks*32 + ((lane>>4)<<4));
                ldm_x4(bfr[p], bbuf + SWZ(off));
            }
            #pragma unroll
            for (int mi = 0; mi < 2; mi++)
                #pragma unroll
                for (int ni = 0; ni < 4; ni++)
                    mma_bf16(acc[mi][ni], afr[mi],
                             bfr[ni>>1][ni&1], bfr[ni>>1][2 + (ni&1)]);
        }
        __syncthreads();
    }
    #undef CSTAGE

    #pragma unroll
    for (int ni = 0; ni < 4; ni++){
        int col = n0 + warp_n*32 + ni*8 + (lane & 3)*2;
        float b0 = biasN[col], b1 = biasN[col+1];
        #pragma unroll
        for (int mi = 0; mi < 2; mi++){
            int rbase = m0 + warp_m*32 + mi*16 + (lane >> 2);
            #pragma unroll
            for (int h = 0; h < 2; h++){
                int row = rbase + h*8;
                long ci = (long)row*DM + col;
                outbf[ci]   = __float2bfloat16(acc[mi][ni][h*2+0] + b0);
                outbf[ci+1] = __float2bfloat16(acc[mi][ni][h*2+1] + b1);
            }
        }
    }
}

// ----------------------------- small kernels -----------------------------
__global__ void k_cast(const float* __restrict__ s, bf16* __restrict__ d, int n){
    int i = blockIdx.x*256 + threadIdx.x;
    if (i < n) d[i] = __float2bfloat16(s[i]);
}

__global__ void k_fuse_w(const float* __restrict__ w_tf, const float* __restrict__ b_tf,
                         const float* __restrict__ w_in, const float* __restrict__ b_in)
{
    int d = blockIdx.x;
    int t = threadIdx.x;   // 128
    __shared__ float win_s[CIN];
    __shared__ float red[CIN];
    win_s[t] = w_in[d*CIN + t];
    __syncthreads();
    int i = t;
    for (int kd=0; kd<3; kd++){
        float acc = 0.f;
        for (int o=0;o<CIN;o++) acc += win_s[o]*w_tf[(o*CIN + i)*3 + kd];
        g_Wf_bf[d*K3 + kd*CIN + i] = __float2bfloat16(acc * (1.0f/TT));
    }
    red[t] = win_s[t]*b_tf[t];
    __syncthreads();
    for (int s=64;s>0;s>>=1){ if (t<s) red[t]+=red[t+s]; __syncthreads(); }
    if (t==0) g_bfv[d] = b_in[d] + red[0];
}

__global__ void k_wsm_flat(const float* __restrict__ w_sm){
    int idx = blockIdx.x*256 + threadIdx.x;
    if (idx >= DM*KP) return;
    int o = idx / KP;
    int r = idx % KP;
    int t = r / DM, c = r % DM;
    g_wsm_bf[idx] = __float2bfloat16(w_sm[((long)o*DM + c)*9 + t]);
}

// temporal sums -> channel-last bf16 S_t[b][p][kd*128+i]
__global__ void k_tsum(const float* __restrict__ feat){
    int idx = blockIdx.x*256 + threadIdx.x;
    if (idx >= BB*CIN*HW) return;
    int p = idx % HW;
    int i = (idx/HW) % CIN;
    int b = idx/(HW*CIN);
    const float* f = feat + (((long)b*TT)*CIN + i)*HW + p;
    const long st = (long)CIN*HW;
    float v0=f[0], v1=f[st], v2=f[2*st], v3=f[3*st];
    float s = v0+v1+v2+v3;
    bf16* o = g_St + ((long)b*HW + p)*K3 + i;
    o[0*CIN] = __float2bfloat16(s - v3);
    o[1*CIN] = __float2bfloat16(s);
    o[2*CIN] = __float2bfloat16(s - v0);
}

// add sine pos to channel-last x_t, emit bf16
__global__ void k_addpos_t(){
    int idx = blockIdx.x*256 + threadIdx.x;
    if (idx >= BB*HW*DM) return;
    int d = idx % DM;
    int p = (idx / DM) % HW;
    int y = p / WW, x2 = p % WW;
    const float two_pi = 6.28318530717958647692f;
    int c2, coord;
    if (d < 128){ c2 = d; coord = y; }
    else        { c2 = d-128; coord = x2; }
    int i = c2 >> 1;
    int par = c2 & 1;
    float cn = (float)(coord+1) / (64.0f + 1e-6f) * two_pi;
    float ex = (float)(2*(i>>1)) / 64.0f;
    float dimt = powf(10000.0f, ex);
    float a = cn / dimt;
    float pos = par ? cosf(a) : sinf(a);
    g_xbf[idx] = __float2bfloat16(g_xt[idx] + pos);
}

__global__ void k_init(const float* __restrict__ q_embed, const float* __restrict__ q_pos,
                       const float* __restrict__ boxes0){
    int idx = blockIdx.x*256 + threadIdx.x;
    if (idx < ROWS*DM){
        int qd = idx % (NQ*DM);
        float v = q_embed[qd] + q_pos[qd];
        g_queries[idx] = v;
        g_q_bf[idx] = __float2bfloat16(v);
    }
    if (idx < ROWS*4) g_boxes[idx] = boxes0[idx];
    if (idx < BB*DM*KQ) g_kvt[idx] = __float2bfloat16(0.f);
}

__global__ void k_ref(const float* __restrict__ w_r2, const float* __restrict__ b_r2){
    int idx = blockIdx.x*256 + threadIdx.x;
    if (idx >= ROWS*16) return;
    int r = idx >> 4, j = idx & 15;
    const float* h = g_h1 + (long)r*DM;
    const float* wr = w_r2 + j*DM;
    float acc = 0.f;
    for (int k=0;k<DM;k++) acc += h[k]*wr[k];
    float ro = tanhf(acc + b_r2[j]) * 0.5f;
    int c = j & 1;
    float v = g_boxes[r*4 + c] + ro;
    g_ref[idx] = fminf(fmaxf(v, 0.f), 1.f);
}

// bilinear 3x3-patch sampling from channel-last bf16 f1
__global__ void k_sample(){
    int rp = blockIdx.x;
    int c  = threadIdx.x;
    int b  = rp / (NQ*NP);
    float rx = g_ref[rp*2+0], ry = g_ref[rp*2+1];
    const bf16* f1 = g_f1bf + (long)b*HW*DM;
    float gx0 = rx*2.f - 1.f;
    float gy0 = ry*2.f - 1.f;
    #pragma unroll
    for (int t=0;t<9;t++){
        float ox = (float)(t%3 - 1), oy = (float)(t/3 - 1);
        float gx = gx0 + ox*(2.f/WW);
        float gy = gy0 + oy*(2.f/HH);
        float x = fminf(fmaxf((gx+1.f)*0.5f*(WW-1), 0.f), (float)(WW-1));
        float y = fminf(fmaxf((gy+1.f)*0.5f*(HH-1), 0.f), (float)(HH-1));
        float x0f = floorf(x), y0f = floorf(y);
        float wx = x - x0f, wy = y - y0f;
        int x0 = (int)x0f, y0 = (int)y0f;
        int x1 = min(x0+1, WW-1), y1 = min(y0+1, HH-1);
        float v00 = __bfloat162float(f1[((long)y0*WW + x0)*DM + c]);
        float v01 = __bfloat162float(f1[((long)y0*WW + x1)*DM + c]);
        float v10 = __bfloat162float(f1[((long)y1*WW + x0)*DM + c]);
        float v11 = __bfloat162float(f1[((long)y1*WW + x1)*DM + c]);
        float v = v00*(1.f-wx)*(1.f-wy) + v01*wx*(1.f-wy)
                + v10*(1.f-wx)*wy       + v11*wx*wy;
        g_sampled_bf[(long)rp*KP + t*DM + c] = __float2bfloat16(v);
    }
}

__global__ void k_mean_p(){
    int idx = blockIdx.x*256 + threadIdx.x;
    if (idx >= ROWS*DM) return;
    int k = idx % DM;
    long r = idx / DM;
    const float* p = g_pv + r*NP*DM + k;
    float s = 0.f;
    #pragma unroll
    for (int j=0;j<NP;j++) s += p[(long)j*DM];
    g_pvm_bf[idx] = __float2bfloat16(s * (1.0f/NP));
}

__global__ void k_softmax(){
    int r = blockIdx.x;                 // 0..599 (row offset r*KQ works for [b][300][320])
    float* row = g_attn + (long)r*KQ;
    bf16* orow = g_attn_bf + (long)r*KQ;
    __shared__ float red[128];
    int t = threadIdx.x;
    float m = -1e30f;
    for (int j=t;j<NQ;j+=128) m = fmaxf(m, row[j]);
    red[t]=m; __syncthreads();
    for (int s=64;s>0;s>>=1){ if (t<s) red[t]=fmaxf(red[t],red[t+s]); __syncthreads(); }
    m = red[0]; __syncthreads();
    float sum=0.f;
    for (int j=t;j<NQ;j+=128){ float e=expf(row[j]-m); row[j]=e; sum+=e; }
    red[t]=sum; __syncthreads();
    for (int s=64;s>0;s>>=1){ if (t<s) red[t]+=red[t+s]; __syncthreads(); }
    float inv = 1.f/red[0];
    for (int j=t;j<KQ;j+=128)
        orow[j] = __float2bfloat16(j < NQ ? row[j]*inv : 0.f);
}

__global__ void k_boxupd(const float* __restrict__ w_b2, const float* __restrict__ b_b2){
    int idx = blockIdx.x*256 + threadIdx.x;
    if (idx >= ROWS*4) return;
    int r = idx >> 2, j = idx & 3;
    const float* h = g_hb + (long)r*DM;
    const float* w = w_b2 + j*DM;
    float acc = 0.f;
    for (int k=0;k<DM;k++) acc += h[k]*w[k];
    float delta = 1.f/(1.f + expf(-(acc + b_b2[j])));
    float v = g_boxes[idx] + 0.1f*tanhf(delta - 0.5f);
    g_boxes[idx] = fminf(fmaxf(v, 0.f), 1.f);
}

__global__ void k_final(const float* __restrict__ w_cls, const float* __restrict__ b_cls,
                        float* __restrict__ out){
    int idx = blockIdx.x*256 + threadIdx.x;
    if (idx >= ROWS + ROWS*4) return;
    if (idx < ROWS){
        const float* q = g_queries + (long)idx*DM;
        float acc = 0.f;
        for (int k=0;k<DM;k++) acc += q[k]*w_cls[k];
        out[idx] = acc + b_cls[0];
    } else {
        out[idx] = g_boxes[idx - ROWS];
    }
}

// ----------------------------- launcher -----------------------------
static inline int ceil_div(int a, int b){ return (a+b-1)/b; }

extern "C" void kernel_launch(void* const* d_in, const int* in_sizes, int n_in,
                              void* d_out, int out_size)
{
    const float* feat    = (const float*)d_in[0];
    const float* boxes0  = (const float*)d_in[1];
    const float* w_tf    = (const float*)d_in[2];
    const float* b_tf    = (const float*)d_in[3];
    const float* w_in    = (const float*)d_in[4];
    const float* b_in    = (const float*)d_in[5];
    const float* w_lat   = (const float*)d_in[6];
    const float* b_lat   = (const float*)d_in[7];
    const float* w_sm    = (const float*)d_in[8];
    const float* b_sm    = (const float*)d_in[9];
    const float* q_embed = (const float*)d_in[10];
    const float* q_pos   = (const float*)d_in[11];
    const float* Wq      = (const float*)d_in[12];
    const float* bq      = (const float*)d_in[13];
    const float* Wo      = (const float*)d_in[14];
    const float* bo      = (const float*)d_in[15];
    const float* Wp1     = (const float*)d_in[16];
    const float* bp1     = (const float*)d_in[17];
    const float* Wp2     = (const float*)d_in[18];
    const float* bp2     = (const float*)d_in[19];
    const float* w_r1    = (const float*)d_in[20];
    const float* b_r1    = (const float*)d_in[21];
    const float* w_r2    = (const float*)d_in[22];
    const float* b_r2    = (const float*)d_in[23];
    const float* w_b1    = (const float*)d_in[24];
    const float* b_b1    = (const float*)d_in[25];
    const float* w_b2    = (const float*)d_in[26];
    const float* b_b2    = (const float*)d_in[27];
    const float* w_cls   = (const float*)d_in[28];
    const float* b_cls   = (const float*)d_in[29];
    float* out = (float*)d_out;

    float *pbfv, *pxt, *pq, *ph1, *phb, *ppv, *pattn;
    bf16 *pSt, *pWfb, *pxbf, *platbf, *pf1bf, *pwsmb, *pwlatb, *pwr1b, *pwb1b;
    bf16 *pWqb, *pWob, *pWp2b, *pWp1b, *pqbf, *psamp, *ppvmb, *pkvb, *pkvt, *pqqb, *pattnb, *paob;
    cudaGetSymbolAddress((void**)&pSt,    g_St);
    cudaGetSymbolAddress((void**)&pWfb,   g_Wf_bf);
    cudaGetSymbolAddress((void**)&pbfv,   g_bfv);
    cudaGetSymbolAddress((void**)&pxt,    g_xt);
    cudaGetSymbolAddress((void**)&pxbf,   g_xbf);
    cudaGetSymbolAddress((void**)&platbf, g_latbf);
    cudaGetSymbolAddress((void**)&pf1bf,  g_f1bf);
    cudaGetSymbolAddress((void**)&pwsmb,  g_wsm_bf);
    cudaGetSymbolAddress((void**)&pwlatb, g_wlat_bf);
    cudaGetSymbolAddress((void**)&pwr1b,  g_wr1_bf);
    cudaGetSymbolAddress((void**)&pwb1b,  g_wb1_bf);
    cudaGetSymbolAddress((void**)&pWqb,   g_Wq_bf);
    cudaGetSymbolAddress((void**)&pWob,   g_Wo_bf);
    cudaGetSymbolAddress((void**)&pWp2b,  g_Wp2_bf);
    cudaGetSymbolAddress((void**)&pWp1b,  g_Wp1_bf);
    cudaGetSymbolAddress((void**)&pq,     g_queries);
    cudaGetSymbolAddress((void**)&pqbf,   g_q_bf);
    cudaGetSymbolAddress((void**)&ph1,    g_h1);
    cudaGetSymbolAddress((void**)&phb,    g_hb);
    cudaGetSymbolAddress((void**)&psamp,  g_sampled_bf);
    cudaGetSymbolAddress((void**)&ppv,    g_pv);
    cudaGetSymbolAddress((void**)&ppvmb,  g_pvm_bf);
    cudaGetSymbolAddress((void**)&pkvb,   g_kv_bf);
    cudaGetSymbolAddress((void**)&pkvt,   g_kvt);
    cudaGetSymbolAddress((void**)&pqqb,   g_qq_bf);
    cudaGetSymbolAddress((void**)&pattn,  g_attn);
    cudaGetSymbolAddress((void**)&pattnb, g_attn_bf);
    cudaGetSymbolAddress((void**)&paob,   g_ao_bf);

    // ---------------- prologue: weight prep ----------------
    k_fuse_w<<<DM, CIN>>>(w_tf, b_tf, w_in, b_in);
    k_wsm_flat<<<ceil_div(DM*KP,256), 256>>>(w_sm);
    k_cast<<<ceil_div(DM*DM,256),256>>>(w_lat, pwlatb, DM*DM);
    k_cast<<<ceil_div(DM*DM,256),256>>>(w_r1,  pwr1b,  DM*DM);
    k_cast<<<ceil_div(DM*DM,256),256>>>(w_b1,  pwb1b,  DM*DM);
    k_cast<<<ceil_div(NL*DM*DM,256),256>>>(Wq,  pWqb,  NL*DM*DM);
    k_cast<<<ceil_div(NL*DM*DM,256),256>>>(Wo,  pWob,  NL*DM*DM);
    k_cast<<<ceil_div(NL*DM*DM,256),256>>>(Wp2, pWp2b, NL*DM*DM);
    k_cast<<<ceil_div(NL*DM*KP,256),256>>>(Wp1, pWp1b, NL*DM*KP);
    k_tsum<<<ceil_div(BB*CIN*HW,256), 256>>>(feat);

    // ---------------- backbone ----------------
    // x_t[b][p][d] = S_t[b][p][:] . Wf[d][:] + bf   (M=HW, N=DM, K=384)
    k_hmma<<<dim3(HW/64, DM/128, BB), 256>>>(
        pSt, pWfb, pbfv, nullptr, pxt, nullptr, nullptr,
        HW, DM, K3, K3, K3, DM,
        (long)HW*K3, 0, (long)HW*DM, 0, 1.0f);
    k_addpos_t<<<ceil_div(BB*HW*DM,256), 256>>>();

    // lat[b][p][o] = x_bf[b][p][:] . w_lat[o][:] + b_lat  -> bf16
    k_hmma<<<dim3(HW/64, DM/128, BB), 256>>>(
        pxbf, pwlatb, b_lat, nullptr, nullptr, platbf, nullptr,
        HW, DM, DM, DM, DM, DM,
        (long)HW*DM, 0, (long)HW*DM, 0, 1.0f);

    // conv3x3 -> f1 bf16 channel-last
    k_conv_hmma<<<dim3(BB*HW/64, DM/128), 256>>>(platbf, pwsmb, b_sm, pf1bf);

    k_init<<<ceil_div(BB*DM*KQ,256), 256>>>(q_embed, q_pos, boxes0);

    const float inv_sqrt_d = 0.0625f;

    // ---------------- decoder ----------------
    for (int l=0; l<NL; l++){
        const float* bq_l  = bq  + (long)l*DM;
        const float* bo_l  = bo  + (long)l*DM;
        const float* bp1_l = bp1 + (long)l*DM;
        const float* bp2_l = bp2 + (long)l*DM;
        bf16* Wq_l  = pWqb  + (long)l*DM*DM;
        bf16* Wo_l  = pWob  + (long)l*DM*DM;
        bf16* Wp2_l = pWp2b + (long)l*DM*DM;
        bf16* Wp1_l = pWp1b + (long)l*DM*KP;

        // h1 = relu(q_bf @ w_r1^T + b_r1) -> fp32
        k_hmma<<<dim3(ceil_div(ROWS,64), DM/128, 1), 256>>>(
            pqbf, pwr1b, b_r1, nullptr, ph1, nullptr, nullptr,
            ROWS, DM, DM, DM, DM, DM, 0,0,0, 1, 1.0f);

        k_ref<<<ceil_div(ROWS*16,256), 256>>>(w_r2, b_r2);
        k_sample<<<RP, DM>>>();

        // pv = relu(sampled @ Wp1^T + bp1) -> fp32
        k_hmma<<<dim3(RP/64, DM/128, 1), 256>>>(
            psamp, Wp1_l, bp1_l, nullptr, ppv, nullptr, nullptr,
            RP, DM, KP, KP, KP, DM, 0,0,0, 1, 1.0f);

        k_mean_p<<<ceil_div(ROWS*DM,256), 256>>>();

        // kv = pvm_bf @ Wp2^T + bp2 -> bf16 (+ transposed)
        k_hmma<<<dim3(ceil_div(ROWS,64), DM/128, 1), 256>>>(
            ppvmb, Wp2_l, bp2_l, nullptr, nullptr, pkvb, pkvt,
            ROWS, DM, DM, DM, DM, DM, 0,0,0, 0, 1.0f);

        // q = q_bf @ Wq^T + bq -> bf16
        k_hmma<<<dim3(ceil_div(ROWS,64), DM/128, 1), 256>>>(
            pqbf, Wq_l, bq_l, nullptr, nullptr, pqqb, nullptr,
            ROWS, DM, DM, DM, DM, DM, 0,0,0, 0, 1.0f);

        // logits[b] = (q[b] @ kv[b]^T) / 16 -> fp32 (ldc=KQ)
        k_hmma<<<dim3(ceil_div(NQ,64), ceil_div(NQ,128), BB), 256>>>(
            pqqb, pkvb, nullptr, nullptr, pattn, nullptr, nullptr,
            NQ, NQ, DM, DM, DM, KQ,
            (long)NQ*DM, (long)NQ*DM, (long)NQ*KQ, 0, inv_sqrt_d);

        k_softmax<<<ROWS, 128>>>();

        // att_out[b] = attn_bf[b] @ kvt[b]^T -> bf16
        k_hmma<<<dim3(ceil_div(NQ,64), DM/128, BB), 256>>>(
            pattnb, pkvt, nullptr, nullptr, nullptr, paob, nullptr,
            NQ, DM, KQ, KQ, KQ, DM,
            (long)NQ*KQ, (long)DM*KQ, (long)NQ*DM, 0, 1.0f);

        // queries += att_out @ Wo^T + bo  (fp32 residual, dual-write bf16)
        k_hmma<<<dim3(ceil_div(ROWS,64), DM/128, 1), 256>>>(
            paob, Wo_l, bo_l, pq, pq, pqbf, nullptr,
            ROWS, DM, DM, DM, DM, DM, 0,0,0, 0, 1.0f);

        // hb = relu(q_bf @ w_b1^T + b_b1) -> fp32
        k_hmma<<<dim3(ceil_div(ROWS,64), DM/128, 1), 256>>>(
            pqbf, pwb1b, b_b1, nullptr, phb, nullptr, nullptr,
            ROWS, DM, DM, DM, DM, DM, 0,0,0, 1, 1.0f);

        k_boxupd<<<ceil_div(ROWS*4,256), 256>>>(w_b2, b_b2);
    }

    k_final<<<ceil_div(ROWS*5,256), 256>>>(w_cls, b_cls, out);
}

// round 10
// speedup vs baseline: 7.2127x; 1.0803x over previous
#include <cuda_runtime.h>
#include <cuda_bf16.h>
#include <math.h>
#include <stdint.h>

#define BB 2
#define TT 4
#define CIN 128
#define HH 64
#define WW 64
#define DM 256
#define NQ 300
#define NP 8
#define PS 3
#define NL 6
#define HW (HH*WW)          // 4096
#define ROWS (BB*NQ)        // 600
#define RP (BB*NQ*NP)       // 4800
#define KP (PS*PS*DM)       // 2304
#define K3 (3*CIN)          // 384
#define KQ 320              // padded attn K (300 -> 320)
#define SMEM_DYN 73728      // 3*(8KB A + 16KB B)

typedef __nv_bfloat16 bf16;

// ----------------------------- scratch (device globals) -----------------------------
__device__ bf16  g_St[BB*HW*K3];
__device__ bf16  g_Wf_bf[DM*K3];
__device__ float g_bfv[DM];
__device__ float g_xt[BB*HW*DM];
__device__ bf16  g_xbf[BB*HW*DM];
__device__ bf16  g_latbf[BB*HW*DM];
__device__ bf16  g_f1bf[BB*HW*DM];
__device__ bf16  g_wsm_bf[DM*KP];
__device__ bf16  g_wlat_bf[DM*DM];
__device__ bf16  g_wb1_bf[DM*DM];
__device__ bf16  g_wcat[NL*2*DM*DM];    // stacked [w_r1; Wq_l] per layer
__device__ float g_bcat[NL*2*DM];
__device__ bf16  g_Wo_bf[NL*DM*DM];
__device__ bf16  g_Wp2_bf[NL*DM*DM];
__device__ bf16  g_Wp1_bf[NL*DM*KP];
__device__ float g_queries[ROWS*DM];
__device__ bf16  g_q_bf[ROWS*DM];
__device__ float g_boxes[ROWS*4];
__device__ float g_h1[ROWS*DM];
__device__ float g_hb[ROWS*DM];
__device__ float g_ref[ROWS*NP*2];
__device__ bf16  g_sampled_bf[RP*KP];
__device__ bf16  g_pv_bf[RP*DM];
__device__ bf16  g_pvm_bf[ROWS*DM];
__device__ bf16  g_kv_bf[ROWS*DM];
__device__ bf16  g_kvt[BB*DM*KQ];
__device__ bf16  g_qq_bf[ROWS*DM];
__device__ float g_attn[ROWS*KQ];
__device__ bf16  g_attn_bf[ROWS*KQ];
__device__ bf16  g_ao_bf[ROWS*DM];

// ----------------------------- PTX helpers -----------------------------
__device__ __forceinline__ uint32_t smem_u32(const void* p){
    uint32_t a;
    asm("{ .reg .u64 t; cvta.to.shared.u64 t, %1; cvt.u32.u64 %0, t; }" : "=r"(a) : "l"(p));
    return a;
}
__device__ __forceinline__ void cp_async16z(uint32_t dst, const void* src, uint32_t sz){
    asm volatile("cp.async.cg.shared.global [%0], [%1], 16, %2;" :: "r"(dst), "l"(src), "r"(sz) : "memory");
}
__device__ __forceinline__ void ldm_x4(uint32_t* r, uint32_t addr){
    asm volatile("ldmatrix.sync.aligned.m8n8.x4.shared.b16 {%0,%1,%2,%3}, [%4];"
                 : "=r"(r[0]), "=r"(r[1]), "=r"(r[2]), "=r"(r[3]) : "r"(addr));
}
__device__ __forceinline__ void mma_bf16(float* c, const uint32_t* a, uint32_t b0, uint32_t b1){
    asm volatile("mma.sync.aligned.m16n8k16.row.col.f32.bf16.bf16.f32 "
                 "{%0,%1,%2,%3}, {%4,%5,%6,%7}, {%8,%9}, {%0,%1,%2,%3};"
                 : "+f"(c[0]), "+f"(c[1]), "+f"(c[2]), "+f"(c[3])
                 : "r"(a[0]), "r"(a[1]), "r"(a[2]), "r"(a[3]), "r"(b0), "r"(b1));
}
#define SWZ(off) ((off) ^ (((off) >> 3) & 0x70))

// ===================================================================================
// Generic bf16 HMMA NT GEMM, 3-stage cp.async pipeline.
// C[z][m][n] = act( alpha * sum_k A[..m,k] * B[..n,k] + biasN[n] + Cres )
// splitN>0: cols<splitN -> Cf with relu; cols>=splitN -> Cb (no relu) at col-splitN.
// BM=64, BN=128, BK=64. grid (ceil(M/64), ceil(N/128), Z). K multiple of 64.
// ===================================================================================
__global__ void __launch_bounds__(256) k_hmma(
    const bf16* __restrict__ A, const bf16* __restrict__ B,
    const float* __restrict__ biasN, const float* __restrict__ Cres,
    float* __restrict__ Cf, bf16* __restrict__ Cb, bf16* __restrict__ Ct,
    int M, int N, int K, int lda, int ldb, int ldc,
    long sA, long sB, long sC,
    int act, float alpha, int splitN)
{
    extern __shared__ __align__(128) char smem[];
    const uint32_t sb = smem_u32(smem);
    const int tid = threadIdx.x;
    const int lane = tid & 31, wid = tid >> 5;
    const int warp_m = wid & 1;
    const int warp_n = wid >> 1;
    const int m0 = blockIdx.x * 64;
    const int n0 = blockIdx.y * 128;
    const long zo = blockIdx.z;
    const bf16* Ab = A + zo * sA;
    const bf16* Bb = B + zo * sB;
    const int nit = K >> 6;

    float acc[2][4][4];
    #pragma unroll
    for (int mi=0;mi<2;mi++)
        #pragma unroll
        for (int ni=0;ni<4;ni++)
            #pragma unroll
            for (int c=0;c<4;c++) acc[mi][ni][c]=0.f;

    #define STAGE(IT) do { \
        int kk = (IT) * 64; \
        uint32_t abuf = sb + ((IT)%3)*8192; \
        uint32_t bbuf = sb + 24576 + ((IT)%3)*16384; \
        for (int e = tid; e < 512; e += 256){ \
            int r = e >> 3, c = e & 7; \
            int gm = m0 + r; \
            int rm = gm < M ? gm : 0; \
            uint32_t sz = gm < M ? 16u : 0u; \
            uint32_t off = (uint32_t)(r*128 + c*16); \
            cp_async16z(abuf + SWZ(off), Ab + (size_t)rm*lda + kk + c*8, sz); \
        } \
        for (int e = tid; e < 1024; e += 256){ \
            int r = e >> 3, c = e & 7; \
            int gn = n0 + r; \
            int rn = gn < N ? gn : 0; \
            uint32_t sz = gn < N ? 16u : 0u; \
            uint32_t off = (uint32_t)(r*128 + c*16); \
            cp_async16z(bbuf + SWZ(off), Bb + (size_t)rn*ldb + kk + c*8, sz); \
        } \
        asm volatile("cp.async.commit_group;" ::: "memory"); \
    } while(0)

    STAGE(0);
    if (nit > 1) STAGE(1);
    for (int it = 0; it < nit; it++){
        if (it < nit-1) asm volatile("cp.async.wait_group 1;" ::: "memory");
        else            asm volatile("cp.async.wait_group 0;" ::: "memory");
        __syncthreads();
        if (it + 2 < nit) STAGE(it+2);
        uint32_t abuf = sb + (it%3)*8192;
        uint32_t bbuf = sb + 24576 + (it%3)*16384;
        #pragma unroll
        for (int ks = 0; ks < 4; ks++){
            uint32_t afr[2][4], bfr[2][4];
            #pragma unroll
            for (int mi = 0; mi < 2; mi++){
                int row = warp_m*32 + mi*16 + (lane & 15);
                uint32_t off = (uint32_t)(row*128 + ks*32 + ((lane>>4)<<4));
                ldm_x4(afr[mi], abuf + SWZ(off));
            }
            #pragma unroll
            for (int p = 0; p < 2; p++){
                int row = warp_n*32 + p*16 + (lane & 15);
                uint32_t off = (uint32_t)(row*128 + ks*32 + ((lane>>4)<<4));
                ldm_x4(bfr[p], bbuf + SWZ(off));
            }
            #pragma unroll
            for (int mi = 0; mi < 2; mi++)
                #pragma unroll
                for (int ni = 0; ni < 4; ni++)
                    mma_bf16(acc[mi][ni], afr[mi],
                             bfr[ni>>1][ni&1], bfr[ni>>1][2 + (ni&1)]);
        }
    }
    #undef STAGE

    // ---- epilogue ----
    #pragma unroll
    for (int ni = 0; ni < 4; ni++){
        int col = n0 + warp_n*32 + ni*8 + (lane & 3)*2;
        bool cok = col < N;
        float b0 = (cok && biasN) ? biasN[col]   : 0.f;
        float b1 = (cok && biasN) ? biasN[col+1] : 0.f;
        #pragma unroll
        for (int mi = 0; mi < 2; mi++){
            int rbase = m0 + warp_m*32 + mi*16 + (lane >> 2);
            #pragma unroll
            for (int h = 0; h < 2; h++){
                int row = rbase + h*8;
                if (row >= M || !cok) continue;
                float v0 = acc[mi][ni][h*2+0]*alpha + b0;
                float v1 = acc[mi][ni][h*2+1]*alpha + b1;
                if (splitN > 0){
                    if (col < splitN){
                        v0 = fmaxf(v0, 0.f); v1 = fmaxf(v1, 0.f);
                        long ci = (long)row*ldc + col;
                        Cf[ci] = v0; Cf[ci+1] = v1;
                    } else {
                        long ci = (long)row*ldc + (col - splitN);
                        Cb[ci] = __float2bfloat16(v0); Cb[ci+1] = __float2bfloat16(v1);
                    }
                    continue;
                }
                long ci = zo*sC + (long)row*ldc + col;
                if (Cres){ v0 += Cres[ci]; v1 += Cres[ci+1]; }
                if (act){ v0 = fmaxf(v0, 0.f); v1 = fmaxf(v1, 0.f); }
                if (Cf){ Cf[ci] = v0; Cf[ci+1] = v1; }
                if (Cb){ Cb[ci] = __float2bfloat16(v0); Cb[ci+1] = __float2bfloat16(v1); }
                if (Ct){
                    int bq = row / NQ, q = row % NQ;
                    long t0 = (long)bq*DM*KQ + (long)col*KQ + q;
                    Ct[t0]      = __float2bfloat16(v0);
                    Ct[t0 + KQ] = __float2bfloat16(v1);
                }
            }
        }
    }
}

// ===================================================================================
// conv3x3 im2col HMMA, 3-stage. M=BB*HW, N=256, K=2304.
// ===================================================================================
__global__ void __launch_bounds__(256) k_conv_hmma(
    const bf16* __restrict__ latbf, const bf16* __restrict__ Wt,
    const float* __restrict__ biasN, bf16* __restrict__ outbf)
{
    extern __shared__ __align__(128) char smem[];
    const uint32_t sb = smem_u32(smem);
    const int tid = threadIdx.x;
    const int lane = tid & 31, wid = tid >> 5;
    const int warp_m = wid & 1;
    const int warp_n = wid >> 1;
    const int m0 = blockIdx.x * 64;
    const int n0 = blockIdx.y * 128;
    const int bimg = m0 >> 12;
    const int yimg = (m0 >> 6) & 63;
    const int nit = KP >> 6;   // 36

    float acc[2][4][4];
    #pragma unroll
    for (int mi=0;mi<2;mi++)
        #pragma unroll
        for (int ni=0;ni<4;ni++)
            #pragma unroll
            for (int c=0;c<4;c++) acc[mi][ni][c]=0.f;

    #define CSTAGE(IT) do { \
        int kk = (IT) * 64; \
        int tap = kk >> 8; \
        int kc  = kk & 255; \
        int dy = tap/3 - 1, dx = tap%3 - 1; \
        int yy = yimg + dy; \
        uint32_t abuf = sb + ((IT)%3)*8192; \
        uint32_t bbuf = sb + 24576 + ((IT)%3)*16384; \
        for (int e = tid; e < 512; e += 256){ \
            int r = e >> 3, c = e & 7; \
            int xx = r + dx; \
            bool ok = (yy >= 0 && yy < HH && xx >= 0 && xx < WW); \
            int pix = bimg*HW + (ok ? (yy*WW + xx) : 0); \
            uint32_t sz = ok ? 16u : 0u; \
            uint32_t off = (uint32_t)(r*128 + c*16); \
            cp_async16z(abuf + SWZ(off), latbf + (size_t)pix*DM + kc + c*8, sz); \
        } \
        for (int e = tid; e < 1024; e += 256){ \
            int r = e >> 3, c = e & 7; \
            uint32_t off = (uint32_t)(r*128 + c*16); \
            cp_async16z(bbuf + SWZ(off), Wt + (size_t)(n0+r)*KP + kk + c*8, 16u); \
        } \
        asm volatile("cp.async.commit_group;" ::: "memory"); \
    } while(0)

    CSTAGE(0);
    CSTAGE(1);
    for (int it = 0; it < nit; it++){
        if (it < nit-1) asm volatile("cp.async.wait_group 1;" ::: "memory");
        else            asm volatile("cp.async.wait_group 0;" ::: "memory");
        __syncthreads();
        if (it + 2 < nit) CSTAGE(it+2);
        uint32_t abuf = sb + (it%3)*8192;
        uint32_t bbuf = sb + 24576 + (it%3)*16384;
        #pragma unroll
        for (int ks = 0; ks < 4; ks++){
            uint32_t afr[2][4], bfr[2][4];
            #pragma unroll
            for (int mi = 0; mi < 2; mi++){
                int row = warp_m*32 + mi*16 + (lane & 15);
                uint32_t off = (uint32_t)(row*128 + ks*32 + ((lane>>4)<<4));
                ldm_x4(afr[mi], abuf + SWZ(off));
            }
            #pragma unroll
            for (int p = 0; p < 2; p++){
                int row = warp_n*32 + p*16 + (lane & 15);
                uint32_t off = (uint32_t)(row*128 + ks*32 + ((lane>>4)<<4));
                ldm_x4(bfr[p], bbuf + SWZ(off));
            }
            #pragma unroll
            for (int mi = 0; mi < 2; mi++)
                #pragma unroll
                for (int ni = 0; ni < 4; ni++)
                    mma_bf16(acc[mi][ni], afr[mi],
                             bfr[ni>>1][ni&1], bfr[ni>>1][2 + (ni&1)]);
        }
    }
    #undef CSTAGE

    #pragma unroll
    for (int ni = 0; ni < 4; ni++){
        int col = n0 + warp_n*32 + ni*8 + (lane & 3)*2;
        float b0 = biasN[col], b1 = biasN[col+1];
        #pragma unroll
        for (int mi = 0; mi < 2; mi++){
            int rbase = m0 + warp_m*32 + mi*16 + (lane >> 2);
            #pragma unroll
            for (int h = 0; h < 2; h++){
                int row = rbase + h*8;
                long ci = (long)row*DM + col;
                outbf[ci]   = __float2bfloat16(acc[mi][ni][h*2+0] + b0);
                outbf[ci+1] = __float2bfloat16(acc[mi][ni][h*2+1] + b1);
            }
        }
    }
}

// ----------------------------- small kernels -----------------------------
__global__ void k_cast(const float* __restrict__ s, bf16* __restrict__ d, int n){
    int i = blockIdx.x*256 + threadIdx.x;
    if (i < n) d[i] = __float2bfloat16(s[i]);
}

// stacked [w_r1; Wq_l] weights + biases
__global__ void k_prep_cat(const float* __restrict__ w_r1, const float* __restrict__ b_r1,
                           const float* __restrict__ Wq, const float* __restrict__ bq){
    int idx = blockIdx.x*256 + threadIdx.x;
    if (idx < NL*2*DM*DM){
        int l = idx / (2*DM*DM);
        int r = (idx / DM) % (2*DM);
        int c = idx % DM;
        float v = (r < DM) ? w_r1[r*DM + c] : Wq[(long)l*DM*DM + (r-DM)*DM + c];
        g_wcat[idx] = __float2bfloat16(v);
    }
    if (idx < NL*2*DM){
        int l = idx / (2*DM);
        int r = idx % (2*DM);
        g_bcat[idx] = (r < DM) ? b_r1[r] : bq[l*DM + r - DM];
    }
}

__global__ void k_fuse_w(const float* __restrict__ w_tf, const float* __restrict__ b_tf,
                         const float* __restrict__ w_in, const float* __restrict__ b_in)
{
    int d = blockIdx.x;
    int t = threadIdx.x;   // 128
    __shared__ float win_s[CIN];
    __shared__ float red[CIN];
    win_s[t] = w_in[d*CIN + t];
    __syncthreads();
    int i = t;
    for (int kd=0; kd<3; kd++){
        float acc = 0.f;
        for (int o=0;o<CIN;o++) acc += win_s[o]*w_tf[(o*CIN + i)*3 + kd];
        g_Wf_bf[d*K3 + kd*CIN + i] = __float2bfloat16(acc * (1.0f/TT));
    }
    red[t] = win_s[t]*b_tf[t];
    __syncthreads();
    for (int s=64;s>0;s>>=1){ if (t<s) red[t]+=red[t+s]; __syncthreads(); }
    if (t==0) g_bfv[d] = b_in[d] + red[0];
}

__global__ void k_wsm_flat(const float* __restrict__ w_sm){
    int idx = blockIdx.x*256 + threadIdx.x;
    if (idx >= DM*KP) return;
    int o = idx / KP;
    int r = idx % KP;
    int t = r / DM, c = r % DM;
    g_wsm_bf[idx] = __float2bfloat16(w_sm[((long)o*DM + c)*9 + t]);
}

__global__ void k_tsum(const float* __restrict__ feat){
    int idx = blockIdx.x*256 + threadIdx.x;
    if (idx >= BB*CIN*HW) return;
    int p = idx % HW;
    int i = (idx/HW) % CIN;
    int b = idx/(HW*CIN);
    const float* f = feat + (((long)b*TT)*CIN + i)*HW + p;
    const long st = (long)CIN*HW;
    float v0=f[0], v1=f[st], v2=f[2*st], v3=f[3*st];
    float s = v0+v1+v2+v3;
    bf16* o = g_St + ((long)b*HW + p)*K3 + i;
    o[0*CIN] = __float2bfloat16(s - v3);
    o[1*CIN] = __float2bfloat16(s);
    o[2*CIN] = __float2bfloat16(s - v0);
}

__global__ void k_addpos_t(){
    int idx = blockIdx.x*256 + threadIdx.x;
    if (idx >= BB*HW*DM) return;
    int d = idx % DM;
    int p = (idx / DM) % HW;
    int y = p / WW, x2 = p % WW;
    const float two_pi = 6.28318530717958647692f;
    int c2, coord;
    if (d < 128){ c2 = d; coord = y; }
    else        { c2 = d-128; coord = x2; }
    int i = c2 >> 1;
    int par = c2 & 1;
    float cn = (float)(coord+1) / (64.0f + 1e-6f) * two_pi;
    float ex = (float)(2*(i>>1)) / 64.0f;
    float dimt = powf(10000.0f, ex);
    float a = cn / dimt;
    float pos = par ? cosf(a) : sinf(a);
    g_xbf[idx] = __float2bfloat16(g_xt[idx] + pos);
}

__global__ void k_init(const float* __restrict__ q_embed, const float* __restrict__ q_pos,
                       const float* __restrict__ boxes0){
    int idx = blockIdx.x*256 + threadIdx.x;
    if (idx < ROWS*DM){
        int qd = idx % (NQ*DM);
        float v = q_embed[qd] + q_pos[qd];
        g_queries[idx] = v;
        g_q_bf[idx] = __float2bfloat16(v);
    }
    if (idx < ROWS*4) g_boxes[idx] = boxes0[idx];
    if (idx < BB*DM*KQ) g_kvt[idx] = __float2bfloat16(0.f);
}

__global__ void k_ref(const float* __restrict__ w_r2, const float* __restrict__ b_r2){
    int idx = blockIdx.x*256 + threadIdx.x;
    if (idx >= ROWS*16) return;
    int r = idx >> 4, j = idx & 15;
    const float* h = g_h1 + (long)r*DM;
    const float* wr = w_r2 + j*DM;
    float acc = 0.f;
    for (int k=0;k<DM;k++) acc += h[k]*wr[k];
    float ro = tanhf(acc + b_r2[j]) * 0.5f;
    int c = j & 1;
    float v = g_boxes[r*4 + c] + ro;
    g_ref[idx] = fminf(fmaxf(v, 0.f), 1.f);
}

// bilinear 3x3-patch sampling, vectorized: block=(b,q), thread=(point, 8-ch group)
__global__ void __launch_bounds__(256) k_sample(){
    int bq = blockIdx.x;              // 0..599
    int b  = bq / NQ;
    int p  = threadIdx.x >> 5;        // 0..7
    int cg = threadIdx.x & 31;        // 0..31 (8 channels each)
    int rp = bq*NP + p;
    float rx = g_ref[rp*2+0], ry = g_ref[rp*2+1];
    const bf16* f1 = g_f1bf + (long)b*HW*DM;
    float gx0 = rx*2.f - 1.f;
    float gy0 = ry*2.f - 1.f;
    #pragma unroll
    for (int t=0;t<9;t++){
        float ox = (float)(t%3 - 1), oy = (float)(t/3 - 1);
        float gx = gx0 + ox*(2.f/WW);
        float gy = gy0 + oy*(2.f/HH);
        float x = fminf(fmaxf((gx+1.f)*0.5f*(WW-1), 0.f), (float)(WW-1));
        float y = fminf(fmaxf((gy+1.f)*0.5f*(HH-1), 0.f), (float)(HH-1));
        float x0f = floorf(x), y0f = floorf(y);
        float wx = x - x0f, wy = y - y0f;
        int x0 = (int)x0f, y0 = (int)y0f;
        int x1 = min(x0+1, WW-1), y1 = min(y0+1, HH-1);
        float w00 = (1.f-wx)*(1.f-wy), w01 = wx*(1.f-wy);
        float w10 = (1.f-wx)*wy,       w11 = wx*wy;
        uint4 q00 = *((const uint4*)(f1 + ((long)y0*WW + x0)*DM) + cg);
        uint4 q01 = *((const uint4*)(f1 + ((long)y0*WW + x1)*DM) + cg);
        uint4 q10 = *((const uint4*)(f1 + ((long)y1*WW + x0)*DM) + cg);
        uint4 q11 = *((const uint4*)(f1 + ((long)y1*WW + x1)*DM) + cg);
        const uint32_t* a00 = (const uint32_t*)&q00;
        const uint32_t* a01 = (const uint32_t*)&q01;
        const uint32_t* a10 = (const uint32_t*)&q10;
        const uint32_t* a11 = (const uint32_t*)&q11;
        uint4 o;
        uint32_t* o32 = (uint32_t*)&o;
        #pragma unroll
        for (int j = 0; j < 4; j++){
            float2 f00 = __bfloat1622float2(*(const __nv_bfloat162*)&a00[j]);
            float2 f01 = __bfloat1622float2(*(const __nv_bfloat162*)&a01[j]);
            float2 f10 = __bfloat1622float2(*(const __nv_bfloat162*)&a10[j]);
            float2 f11 = __bfloat1622float2(*(const __nv_bfloat162*)&a11[j]);
            float vx = f00.x*w00 + f01.x*w01 + f10.x*w10 + f11.x*w11;
            float vy = f00.y*w00 + f01.y*w01 + f10.y*w10 + f11.y*w11;
            __nv_bfloat162 pk = __floats2bfloat162_rn(vx, vy);
            o32[j] = *(uint32_t*)&pk;
        }
        *((uint4*)(g_sampled_bf + (long)rp*KP + t*DM) + cg) = o;
    }
}

__global__ void k_mean_p(){
    int idx = blockIdx.x*256 + threadIdx.x;
    if (idx >= ROWS*DM) return;
    int k = idx % DM;
    long r = idx / DM;
    const bf16* p = g_pv_bf + r*NP*DM + k;
    float s = 0.f;
    #pragma unroll
    for (int j=0;j<NP;j++) s += __bfloat162float(p[(long)j*DM]);
    g_pvm_bf[idx] = __float2bfloat16(s * (1.0f/NP));
}

__global__ void k_softmax(){
    int r = blockIdx.x;
    float* row = g_attn + (long)r*KQ;
    bf16* orow = g_attn_bf + (long)r*KQ;
    __shared__ float red[128];
    int t = threadIdx.x;
    float m = -1e30f;
    for (int j=t;j<NQ;j+=128) m = fmaxf(m, row[j]);
    red[t]=m; __syncthreads();
    for (int s=64;s>0;s>>=1){ if (t<s) red[t]=fmaxf(red[t],red[t+s]); __syncthreads(); }
    m = red[0]; __syncthreads();
    float sum=0.f;
    for (int j=t;j<NQ;j+=128){ float e=expf(row[j]-m); row[j]=e; sum+=e; }
    red[t]=sum; __syncthreads();
    for (int s=64;s>0;s>>=1){ if (t<s) red[t]+=red[t+s]; __syncthreads(); }
    float inv = 1.f/red[0];
    for (int j=t;j<KQ;j+=128)
        orow[j] = __float2bfloat16(j < NQ ? row[j]*inv : 0.f);
}

__global__ void k_boxupd(const float* __restrict__ w_b2, const float* __restrict__ b_b2){
    int idx = blockIdx.x*256 + threadIdx.x;
    if (idx >= ROWS*4) return;
    int r = idx >> 2, j = idx & 3;
    const float* h = g_hb + (long)r*DM;
    const float* w = w_b2 + j*DM;
    float acc = 0.f;
    for (int k=0;k<DM;k++) acc += h[k]*w[k];
    float delta = 1.f/(1.f + expf(-(acc + b_b2[j])));
    float v = g_boxes[idx] + 0.1f*tanhf(delta - 0.5f);
    g_boxes[idx] = fminf(fmaxf(v, 0.f), 1.f);
}

__global__ void k_final(const float* __restrict__ w_cls, const float* __restrict__ b_cls,
                        float* __restrict__ out){
    int idx = blockIdx.x*256 + threadIdx.x;
    if (idx >= ROWS + ROWS*4) return;
    if (idx < ROWS){
        const float* q = g_queries + (long)idx*DM;
        float acc = 0.f;
        for (int k=0;k<DM;k++) acc += q[k]*w_cls[k];
        out[idx] = acc + b_cls[0];
    } else {
        out[idx] = g_boxes[idx - ROWS];
    }
}

// ----------------------------- launcher -----------------------------
static inline int ceil_div(int a, int b){ return (a+b-1)/b; }

extern "C" void kernel_launch(void* const* d_in, const int* in_sizes, int n_in,
                              void* d_out, int out_size)
{
    const float* feat    = (const float*)d_in[0];
    const float* boxes0  = (const float*)d_in[1];
    const float* w_tf    = (const float*)d_in[2];
    const float* b_tf    = (const float*)d_in[3];
    const float* w_in    = (const float*)d_in[4];
    const float* b_in    = (const float*)d_in[5];
    const float* w_lat   = (const float*)d_in[6];
    const float* b_lat   = (const float*)d_in[7];
    const float* w_sm    = (const float*)d_in[8];
    const float* b_sm    = (const float*)d_in[9];
    const float* q_embed = (const float*)d_in[10];
    const float* q_pos   = (const float*)d_in[11];
    const float* Wq      = (const float*)d_in[12];
    const float* bq      = (const float*)d_in[13];
    const float* Wo      = (const float*)d_in[14];
    const float* bo      = (const float*)d_in[15];
    const float* Wp1     = (const float*)d_in[16];
    const float* bp1     = (const float*)d_in[17];
    const float* Wp2     = (const float*)d_in[18];
    const float* bp2     = (const float*)d_in[19];
    const float* w_r1    = (const float*)d_in[20];
    const float* b_r1    = (const float*)d_in[21];
    const float* w_r2    = (const float*)d_in[22];
    const float* b_r2    = (const float*)d_in[23];
    const float* w_b1    = (const float*)d_in[24];
    const float* b_b1    = (const float*)d_in[25];
    const float* w_b2    = (const float*)d_in[26];
    const float* b_b2    = (const float*)d_in[27];
    const float* w_cls   = (const float*)d_in[28];
    const float* b_cls   = (const float*)d_in[29];
    float* out = (float*)d_out;

    cudaFuncSetAttribute(k_hmma, cudaFuncAttributeMaxDynamicSharedMemorySize, SMEM_DYN);
    cudaFuncSetAttribute(k_conv_hmma, cudaFuncAttributeMaxDynamicSharedMemorySize, SMEM_DYN);

    float *pbfv, *pxt, *pq, *ph1, *phb, *pattn, *pbcat;
    bf16 *pSt, *pWfb, *pxbf, *platbf, *pf1bf, *pwsmb, *pwlatb, *pwb1b, *pwcat;
    bf16 *pWob, *pWp2b, *pWp1b, *pqbf, *psamp, *ppvb, *ppvmb, *pkvb, *pkvt, *pqqb, *pattnb, *paob;
    cudaGetSymbolAddress((void**)&pSt,    g_St);
    cudaGetSymbolAddress((void**)&pWfb,   g_Wf_bf);
    cudaGetSymbolAddress((void**)&pbfv,   g_bfv);
    cudaGetSymbolAddress((void**)&pxt,    g_xt);
    cudaGetSymbolAddress((void**)&pxbf,   g_xbf);
    cudaGetSymbolAddress((void**)&platbf, g_latbf);
    cudaGetSymbolAddress((void**)&pf1bf,  g_f1bf);
    cudaGetSymbolAddress((void**)&pwsmb,  g_wsm_bf);
    cudaGetSymbolAddress((void**)&pwlatb, g_wlat_bf);
    cudaGetSymbolAddress((void**)&pwb1b,  g_wb1_bf);
    cudaGetSymbolAddress((void**)&pwcat,  g_wcat);
    cudaGetSymbolAddress((void**)&pbcat,  g_bcat);
    cudaGetSymbolAddress((void**)&pWob,   g_Wo_bf);
    cudaGetSymbolAddress((void**)&pWp2b,  g_Wp2_bf);
    cudaGetSymbolAddress((void**)&pWp1b,  g_Wp1_bf);
    cudaGetSymbolAddress((void**)&pq,     g_queries);
    cudaGetSymbolAddress((void**)&pqbf,   g_q_bf);
    cudaGetSymbolAddress((void**)&ph1,    g_h1);
    cudaGetSymbolAddress((void**)&phb,    g_hb);
    cudaGetSymbolAddress((void**)&psamp,  g_sampled_bf);
    cudaGetSymbolAddress((void**)&ppvb,   g_pv_bf);
    cudaGetSymbolAddress((void**)&ppvmb,  g_pvm_bf);
    cudaGetSymbolAddress((void**)&pkvb,   g_kv_bf);
    cudaGetSymbolAddress((void**)&pkvt,   g_kvt);
    cudaGetSymbolAddress((void**)&pqqb,   g_qq_bf);
    cudaGetSymbolAddress((void**)&pattn,  g_attn);
    cudaGetSymbolAddress((void**)&pattnb, g_attn_bf);
    cudaGetSymbolAddress((void**)&paob,   g_ao_bf);

    // ---------------- prologue: weight prep ----------------
    k_fuse_w<<<DM, CIN>>>(w_tf, b_tf, w_in, b_in);
    k_wsm_flat<<<ceil_div(DM*KP,256), 256>>>(w_sm);
    k_prep_cat<<<ceil_div(NL*2*DM*DM,256), 256>>>(w_r1, b_r1, Wq, bq);
    k_cast<<<ceil_div(DM*DM,256),256>>>(w_lat, pwlatb, DM*DM);
    k_cast<<<ceil_div(DM*DM,256),256>>>(w_b1,  pwb1b,  DM*DM);
    k_cast<<<ceil_div(NL*DM*DM,256),256>>>(Wo,  pWob,  NL*DM*DM);
    k_cast<<<ceil_div(NL*DM*DM,256),256>>>(Wp2, pWp2b, NL*DM*DM);
    k_cast<<<ceil_div(NL*DM*KP,256),256>>>(Wp1, pWp1b, NL*DM*KP);
    k_tsum<<<ceil_div(BB*CIN*HW,256), 256>>>(feat);

    // ---------------- backbone ----------------
    k_hmma<<<dim3(HW/64, DM/128, BB), 256, SMEM_DYN>>>(
        pSt, pWfb, pbfv, nullptr, pxt, nullptr, nullptr,
        HW, DM, K3, K3, K3, DM,
        (long)HW*K3, 0, (long)HW*DM, 0, 1.0f, 0);
    k_addpos_t<<<ceil_div(BB*HW*DM,256), 256>>>();

    k_hmma<<<dim3(HW/64, DM/128, BB), 256, SMEM_DYN>>>(
        pxbf, pwlatb, b_lat, nullptr, nullptr, platbf, nullptr,
        HW, DM, DM, DM, DM, DM,
        (long)HW*DM, 0, (long)HW*DM, 0, 1.0f, 0);

    k_conv_hmma<<<dim3(BB*HW/64, DM/128), 256, SMEM_DYN>>>(platbf, pwsmb, b_sm, pf1bf);

    k_init<<<ceil_div(BB*DM*KQ,256), 256>>>(q_embed, q_pos, boxes0);

    const float inv_sqrt_d = 0.0625f;

    // ---------------- decoder ----------------
    for (int l=0; l<NL; l++){
        const float* bo_l  = bo  + (long)l*DM;
        const float* bp1_l = bp1 + (long)l*DM;
        const float* bp2_l = bp2 + (long)l*DM;
        bf16* Wo_l  = pWob  + (long)l*DM*DM;
        bf16* Wp2_l = pWp2b + (long)l*DM*DM;
        bf16* Wp1_l = pWp1b + (long)l*DM*KP;
        bf16* Wcat_l = pwcat + (long)l*2*DM*DM;
        float* bcat_l = pbcat + (long)l*2*DM;

        // merged: h1 = relu(q @ w_r1^T + b_r1) -> fp32 ; qq = q @ Wq^T + bq -> bf16
        k_hmma<<<dim3(ceil_div(ROWS,64), (2*DM)/128, 1), 256, SMEM_DYN>>>(
            pqbf, Wcat_l, bcat_l, nullptr, ph1, pqqb, nullptr,
            ROWS, 2*DM, DM, DM, DM, DM, 0,0,0, 1, 1.0f, DM);

        k_ref<<<ceil_div(ROWS*16,256), 256>>>(w_r2, b_r2);
        k_sample<<<ROWS, 256>>>();

        // pv = relu(sampled @ Wp1^T + bp1) -> bf16
        k_hmma<<<dim3(RP/64, DM/128, 1), 256, SMEM_DYN>>>(
            psamp, Wp1_l, bp1_l, nullptr, nullptr, ppvb, nullptr,
            RP, DM, KP, KP, KP, DM, 0,0,0, 1, 1.0f, 0);

        k_mean_p<<<ceil_div(ROWS*DM,256), 256>>>();

        // kv = pvm @ Wp2^T + bp2 -> bf16 (+ transposed)
        k_hmma<<<dim3(ceil_div(ROWS,64), DM/128, 1), 256, SMEM_DYN>>>(
            ppvmb, Wp2_l, bp2_l, nullptr, nullptr, pkvb, pkvt,
            ROWS, DM, DM, DM, DM, DM, 0,0,0, 0, 1.0f, 0);

        // logits[b] = (q[b] @ kv[b]^T) / 16 -> fp32 (ldc=KQ)
        k_hmma<<<dim3(ceil_div(NQ,64), ceil_div(NQ,128), BB), 256, SMEM_DYN>>>(
            pqqb, pkvb, nullptr, nullptr, pattn, nullptr, nullptr,
            NQ, NQ, DM, DM, DM, KQ,
            (long)NQ*DM, (long)NQ*DM, (long)NQ*KQ, 0, inv_sqrt_d, 0);

        k_softmax<<<ROWS, 128>>>();

        // att_out[b] = attn_bf[b] @ kvt[b]^T -> bf16
        k_hmma<<<dim3(ceil_div(NQ,64), DM/128, BB), 256, SMEM_DYN>>>(
            pattnb, pkvt, nullptr, nullptr, nullptr, paob, nullptr,
            NQ, DM, KQ, KQ, KQ, DM,
            (long)NQ*KQ, (long)DM*KQ, (long)NQ*DM, 0, 1.0f, 0);

        // queries += att_out @ Wo^T + bo  (fp32 residual, dual-write bf16)
        k_hmma<<<dim3(ceil_div(ROWS,64), DM/128, 1), 256, SMEM_DYN>>>(
            paob, Wo_l, bo_l, pq, pq, pqbf, nullptr,
            ROWS, DM, DM, DM, DM, DM, 0,0,0, 0, 1.0f, 0);

        // hb = relu(q_bf @ w_b1^T + b_b1) -> fp32
        k_hmma<<<dim3(ceil_div(ROWS,64), DM/128, 1), 256, SMEM_DYN>>>(
            pqbf, pwb1b, b_b1, nullptr, phb, nullptr, nullptr,
            ROWS, DM, DM, DM, DM, DM, 0,0,0, 1, 1.0f, 0);

        k_boxupd<<<ceil_div(ROWS*4,256), 256>>>(w_b2, b_b2);
    }

    k_final<<<ceil_div(ROWS*5,256), 256>>>(w_cls, b_cls, out);
}

// round 15
// speedup vs baseline: 8.1065x; 1.1239x over previous
#include <cuda_runtime.h>
#include <cuda_bf16.h>
#include <math.h>
#include <stdint.h>

#define BB 2
#define TT 4
#define CIN 128
#define HH 64
#define WW 64
#define DM 256
#define NQ 300
#define NP 8
#define PS 3
#define NL 6
#define HW (HH*WW)          // 4096
#define ROWS (BB*NQ)        // 600
#define RP (BB*NQ*NP)       // 4800
#define KP (PS*PS*DM)       // 2304
#define K3 (3*CIN)          // 384
#define KQ 320              // padded attn K (300 -> 320)
#define SMEM_DYN 73728      // 3*(8KB A + 16KB B)
// k_attn smem: A 32KB + B 64KB + scores 64*320*4 = 80KB
#define ATTN_SMEM (32768 + 65536 + 81920)

typedef __nv_bfloat16 bf16;

// ----------------------------- scratch (device globals) -----------------------------
__device__ bf16  g_St[BB*HW*K3];
__device__ bf16  g_Wf_bf[DM*K3];
__device__ float g_bfv[DM];
__device__ bf16  g_xbf[BB*HW*DM];
__device__ bf16  g_latbf[BB*HW*DM];
__device__ bf16  g_f1bf[BB*HW*DM];
__device__ bf16  g_wsm_bf[DM*KP];
__device__ bf16  g_wlat_bf[DM*DM];
__device__ bf16  g_wr1T[DM*DM];        // [k][o]
__device__ bf16  g_wb1T[DM*DM];        // [k][o]
__device__ bf16  g_Wq_bf[NL*DM*DM];
__device__ bf16  g_Wo_bf[NL*DM*DM];
__device__ bf16  g_Wp2_bf[NL*DM*DM];
__device__ bf16  g_Wp1_bf[NL*DM*KP];
__device__ float g_queries[ROWS*DM];
__device__ bf16  g_q_bf[ROWS*DM];
__device__ float g_boxes[ROWS*4];
__device__ bf16  g_sampled_bf[RP*KP];
__device__ bf16  g_pv_bf[RP*DM];
__device__ bf16  g_pvm_bf[ROWS*DM];
__device__ bf16  g_kv_bf[ROWS*DM];
__device__ bf16  g_kvt[BB*DM*KQ];
__device__ bf16  g_qq_bf[ROWS*DM];
__device__ bf16  g_attn_bf[ROWS*KQ];
__device__ bf16  g_ao_bf[ROWS*DM];

// ----------------------------- PTX helpers -----------------------------
__device__ __forceinline__ uint32_t smem_u32(const void* p){
    uint32_t a;
    asm("{ .reg .u64 t; cvta.to.shared.u64 t, %1; cvt.u32.u64 %0, t; }" : "=r"(a) : "l"(p));
    return a;
}
__device__ __forceinline__ void cp_async16z(uint32_t dst, const void* src, uint32_t sz){
    asm volatile("cp.async.cg.shared.global [%0], [%1], 16, %2;" :: "r"(dst), "l"(src), "r"(sz) : "memory");
}
__device__ __forceinline__ void ldm_x4(uint32_t* r, uint32_t addr){
    asm volatile("ldmatrix.sync.aligned.m8n8.x4.shared.b16 {%0,%1,%2,%3}, [%4];"
                 : "=r"(r[0]), "=r"(r[1]), "=r"(r[2]), "=r"(r[3]) : "r"(addr));
}
__device__ __forceinline__ void mma_bf16(float* c, const uint32_t* a, uint32_t b0, uint32_t b1){
    asm volatile("mma.sync.aligned.m16n8k16.row.col.f32.bf16.bf16.f32 "
                 "{%0,%1,%2,%3}, {%4,%5,%6,%7}, {%8,%9}, {%0,%1,%2,%3};"
                 : "+f"(c[0]), "+f"(c[1]), "+f"(c[2]), "+f"(c[3])
                 : "r"(a[0]), "r"(a[1]), "r"(a[2]), "r"(a[3]), "r"(b0), "r"(b1));
}
#define SWZ(off) ((off) ^ (((off) >> 3) & 0x70))

__device__ __forceinline__ float posval(int p, int d){
    int y = p >> 6, x2 = p & 63;
    int c2, coord;
    if (d < 128){ c2 = d; coord = y; } else { c2 = d - 128; coord = x2; }
    int i = c2 >> 1;
    int par = c2 & 1;
    float cn = (float)(coord+1) / (64.0f + 1e-6f) * 6.28318530717958647692f;
    float ex = (float)(2*(i>>1)) / 64.0f;
    float dimt = powf(10000.0f, ex);
    float a = cn / dimt;
    return par ? cosf(a) : sinf(a);
}

// ===================================================================================
// Generic bf16 HMMA NT GEMM, 3-stage cp.async pipeline.
// epmode==1: add sine positional encoding (row=pixel, col=channel), write Cb only.
// ===================================================================================
__global__ void __launch_bounds__(256) k_hmma(
    const bf16* __restrict__ A, const bf16* __restrict__ B,
    const float* __restrict__ biasN, const float* __restrict__ Cres,
    float* __restrict__ Cf, bf16* __restrict__ Cb, bf16* __restrict__ Ct,
    int M, int N, int K, int lda, int ldb, int ldc,
    long sA, long sB, long sC,
    int act, float alpha, int epmode)
{
    extern __shared__ __align__(128) char smem[];
    const uint32_t sb = smem_u32(smem);
    const int tid = threadIdx.x;
    const int lane = tid & 31, wid = tid >> 5;
    const int warp_m = wid & 1;
    const int warp_n = wid >> 1;
    const int m0 = blockIdx.x * 64;
    const int n0 = blockIdx.y * 128;
    const long zo = blockIdx.z;
    const bf16* Ab = A + zo * sA;
    const bf16* Bb = B + zo * sB;
    const int nit = K >> 6;

    float acc[2][4][4];
    #pragma unroll
    for (int mi=0;mi<2;mi++)
        #pragma unroll
        for (int ni=0;ni<4;ni++)
            #pragma unroll
            for (int c=0;c<4;c++) acc[mi][ni][c]=0.f;

    #define STAGE(IT) do { \
        int kk = (IT) * 64; \
        uint32_t abuf = sb + ((IT)%3)*8192; \
        uint32_t bbuf = sb + 24576 + ((IT)%3)*16384; \
        for (int e = tid; e < 512; e += 256){ \
            int r = e >> 3, c = e & 7; \
            int gm = m0 + r; \
            int rm = gm < M ? gm : 0; \
            uint32_t sz = gm < M ? 16u : 0u; \
            uint32_t off = (uint32_t)(r*128 + c*16); \
            cp_async16z(abuf + SWZ(off), Ab + (size_t)rm*lda + kk + c*8, sz); \
        } \
        for (int e = tid; e < 1024; e += 256){ \
            int r = e >> 3, c = e & 7; \
            int gn = n0 + r; \
            int rn = gn < N ? gn : 0; \
            uint32_t sz = gn < N ? 16u : 0u; \
            uint32_t off = (uint32_t)(r*128 + c*16); \
            cp_async16z(bbuf + SWZ(off), Bb + (size_t)rn*ldb + kk + c*8, sz); \
        } \
        asm volatile("cp.async.commit_group;" ::: "memory"); \
    } while(0)

    STAGE(0);
    if (nit > 1) STAGE(1);
    for (int it = 0; it < nit; it++){
        if (it < nit-1) asm volatile("cp.async.wait_group 1;" ::: "memory");
        else            asm volatile("cp.async.wait_group 0;" ::: "memory");
        __syncthreads();
        if (it + 2 < nit) STAGE(it+2);
        uint32_t abuf = sb + (it%3)*8192;
        uint32_t bbuf = sb + 24576 + (it%3)*16384;
        #pragma unroll
        for (int ks = 0; ks < 4; ks++){
            uint32_t afr[2][4], bfr[2][4];
            #pragma unroll
            for (int mi = 0; mi < 2; mi++){
                int row = warp_m*32 + mi*16 + (lane & 15);
                uint32_t off = (uint32_t)(row*128 + ks*32 + ((lane>>4)<<4));
                ldm_x4(afr[mi], abuf + SWZ(off));
            }
            #pragma unroll
            for (int p = 0; p < 2; p++){
                int row = warp_n*32 + p*16 + (lane & 15);
                uint32_t off = (uint32_t)(row*128 + ks*32 + ((lane>>4)<<4));
                ldm_x4(bfr[p], bbuf + SWZ(off));
            }
            #pragma unroll
            for (int mi = 0; mi < 2; mi++)
                #pragma unroll
                for (int ni = 0; ni < 4; ni++)
                    mma_bf16(acc[mi][ni], afr[mi],
                             bfr[ni>>1][ni&1], bfr[ni>>1][2 + (ni&1)]);
        }
    }
    #undef STAGE

    // ---- epilogue ----
    #pragma unroll
    for (int ni = 0; ni < 4; ni++){
        int col = n0 + warp_n*32 + ni*8 + (lane & 3)*2;
        bool cok = col < N;
        float b0 = (cok && biasN) ? biasN[col]   : 0.f;
        float b1 = (cok && biasN) ? biasN[col+1] : 0.f;
        #pragma unroll
        for (int mi = 0; mi < 2; mi++){
            int rbase = m0 + warp_m*32 + mi*16 + (lane >> 2);
            #pragma unroll
            for (int h = 0; h < 2; h++){
                int row = rbase + h*8;
                if (row >= M || !cok) continue;
                float v0 = acc[mi][ni][h*2+0]*alpha + b0;
                float v1 = acc[mi][ni][h*2+1]*alpha + b1;
                long ci = zo*sC + (long)row*ldc + col;
                if (epmode == 1){
                    Cb[ci]   = __float2bfloat16(v0 + posval(row, col));
                    Cb[ci+1] = __float2bfloat16(v1 + posval(row, col+1));
                    continue;
                }
                if (Cres){ v0 += Cres[ci]; v1 += Cres[ci+1]; }
                if (act){ v0 = fmaxf(v0, 0.f); v1 = fmaxf(v1, 0.f); }
                if (Cf){ Cf[ci] = v0; Cf[ci+1] = v1; }
                if (Cb){ Cb[ci] = __float2bfloat16(v0); Cb[ci+1] = __float2bfloat16(v1); }
                if (Ct){
                    int bq = row / NQ, q = row % NQ;
                    long t0 = (long)bq*DM*KQ + (long)col*KQ + q;
                    Ct[t0]      = __float2bfloat16(v0);
                    Ct[t0 + KQ] = __float2bfloat16(v1);
                }
            }
        }
    }
}

// ===================================================================================
// conv3x3 im2col HMMA, 3-stage. M=BB*HW, N=256, K=2304.
// ===================================================================================
__global__ void __launch_bounds__(256) k_conv_hmma(
    const bf16* __restrict__ latbf, const bf16* __restrict__ Wt,
    const float* __restrict__ biasN, bf16* __restrict__ outbf)
{
    extern __shared__ __align__(128) char smem[];
    const uint32_t sb = smem_u32(smem);
    const int tid = threadIdx.x;
    const int lane = tid & 31, wid = tid >> 5;
    const int warp_m = wid & 1;
    const int warp_n = wid >> 1;
    const int m0 = blockIdx.x * 64;
    const int n0 = blockIdx.y * 128;
    const int bimg = m0 >> 12;
    const int yimg = (m0 >> 6) & 63;
    const int nit = KP >> 6;   // 36

    float acc[2][4][4];
    #pragma unroll
    for (int mi=0;mi<2;mi++)
        #pragma unroll
        for (int ni=0;ni<4;ni++)
            #pragma unroll
            for (int c=0;c<4;c++) acc[mi][ni][c]=0.f;

    #define CSTAGE(IT) do { \
        int kk = (IT) * 64; \
        int tap = kk >> 8; \
        int kc  = kk & 255; \
        int dy = tap/3 - 1, dx = tap%3 - 1; \
        int yy = yimg + dy; \
        uint32_t abuf = sb + ((IT)%3)*8192; \
        uint32_t bbuf = sb + 24576 + ((IT)%3)*16384; \
        for (int e = tid; e < 512; e += 256){ \
            int r = e >> 3, c = e & 7; \
            int xx = r + dx; \
            bool ok = (yy >= 0 && yy < HH && xx >= 0 && xx < WW); \
            int pix = bimg*HW + (ok ? (yy*WW + xx) : 0); \
            uint32_t sz = ok ? 16u : 0u; \
            uint32_t off = (uint32_t)(r*128 + c*16); \
            cp_async16z(abuf + SWZ(off), latbf + (size_t)pix*DM + kc + c*8, sz); \
        } \
        for (int e = tid; e < 1024; e += 256){ \
            int r = e >> 3, c = e & 7; \
            uint32_t off = (uint32_t)(r*128 + c*16); \
            cp_async16z(bbuf + SWZ(off), Wt + (size_t)(n0+r)*KP + kk + c*8, 16u); \
        } \
        asm volatile("cp.async.commit_group;" ::: "memory"); \
    } while(0)

    CSTAGE(0);
    CSTAGE(1);
    for (int it = 0; it < nit; it++){
        if (it < nit-1) asm volatile("cp.async.wait_group 1;" ::: "memory");
        else            asm volatile("cp.async.wait_group 0;" ::: "memory");
        __syncthreads();
        if (it + 2 < nit) CSTAGE(it+2);
        uint32_t abuf = sb + (it%3)*8192;
        uint32_t bbuf = sb + 24576 + (it%3)*16384;
        #pragma unroll
        for (int ks = 0; ks < 4; ks++){
            uint32_t afr[2][4], bfr[2][4];
            #pragma unroll
            for (int mi = 0; mi < 2; mi++){
                int row = warp_m*32 + mi*16 + (lane & 15);
                uint32_t off = (uint32_t)(row*128 + ks*32 + ((lane>>4)<<4));
                ldm_x4(afr[mi], abuf + SWZ(off));
            }
            #pragma unroll
            for (int p = 0; p < 2; p++){
                int row = warp_n*32 + p*16 + (lane & 15);
                uint32_t off = (uint32_t)(row*128 + ks*32 + ((lane>>4)<<4));
                ldm_x4(bfr[p], bbuf + SWZ(off));
            }
            #pragma unroll
            for (int mi = 0; mi < 2; mi++)
                #pragma unroll
                for (int ni = 0; ni < 4; ni++)
                    mma_bf16(acc[mi][ni], afr[mi],
                             bfr[ni>>1][ni&1], bfr[ni>>1][2 + (ni&1)]);
        }
    }
    #undef CSTAGE

    #pragma unroll
    for (int ni = 0; ni < 4; ni++){
        int col = n0 + warp_n*32 + ni*8 + (lane & 3)*2;
        float b0 = biasN[col], b1 = biasN[col+1];
        #pragma unroll
        for (int mi = 0; mi < 2; mi++){
            int rbase = m0 + warp_m*32 + mi*16 + (lane >> 2);
            #pragma unroll
            for (int h = 0; h < 2; h++){
                int row = rbase + h*8;
                long ci = (long)row*DM + col;
                outbf[ci]   = __float2bfloat16(acc[mi][ni][h*2+0] + b0);
                outbf[ci+1] = __float2bfloat16(acc[mi][ni][h*2+1] + b1);
            }
        }
    }
}

// ===================================================================================
// Fused attention: logits (qq @ kv^T)/16 + softmax -> attn_bf (padded KQ).
// grid (ceil(NQ/64), 1, BB), 256 threads.
// smem: A[4][64][128B] @0, B[4][128][128B] @32768, scores fp32 [64][320] @98304.
// ===================================================================================
__global__ void __launch_bounds__(256) k_attn(){
    extern __shared__ __align__(128) char smem[];
    const uint32_t sb = smem_u32(smem);
    float* scores = (float*)(smem + 98304);
    const int tid = threadIdx.x;
    const int lane = tid & 31, wid = tid >> 5;
    const int warp_m = wid & 1;
    const int warp_n = wid >> 1;
    const int m0 = blockIdx.x * 64;
    const int b  = blockIdx.z;
    const bf16* Ap = g_qq_bf + (long)b*NQ*DM;
    const bf16* Bp = g_kv_bf + (long)b*NQ*DM;

    // stage A (64 rows x 256 cols) once: 2048 16B-chunks
    for (int e = tid; e < 2048; e += 256){
        int r = e >> 5, c = e & 31;
        int kb = c >> 3, cc = c & 7;
        int gm = m0 + r;
        uint32_t sz = gm < NQ ? 16u : 0u;
        int rm = gm < NQ ? gm : 0;
        uint32_t off = (uint32_t)(r*128 + cc*16);
        cp_async16z(sb + kb*8192 + SWZ(off), Ap + (size_t)rm*DM + kb*64 + cc*8, sz);
    }
    asm volatile("cp.async.commit_group;" ::: "memory");

    for (int nt = 0; nt < 3; nt++){
        // stage B tile: kv rows nt*128 .. +127, full K=256
        for (int e = tid; e < 4096; e += 256){
            int r = e >> 5, c = e & 31;
            int kb = c >> 3, cc = c & 7;
            int gn = nt*128 + r;
            uint32_t sz = gn < NQ ? 16u : 0u;
            int rn = gn < NQ ? gn : 0;
            uint32_t off = (uint32_t)(r*128 + cc*16);
            cp_async16z(sb + 32768 + kb*16384 + SWZ(off), Bp + (size_t)rn*DM + kb*64 + cc*8, sz);
        }
        asm volatile("cp.async.commit_group;" ::: "memory");
        asm volatile("cp.async.wait_group 0;" ::: "memory");
        __syncthreads();

        float acc[2][4][4];
        #pragma unroll
        for (int mi=0;mi<2;mi++)
            #pragma unroll
            for (int ni=0;ni<4;ni++)
                #pragma unroll
                for (int c=0;c<4;c++) acc[mi][ni][c]=0.f;

        #pragma unroll
        for (int kb = 0; kb < 4; kb++){
            uint32_t abuf = sb + kb*8192;
            uint32_t bbuf = sb + 32768 + kb*16384;
            #pragma unroll
            for (int ks = 0; ks < 4; ks++){
                uint32_t afr[2][4], bfr[2][4];
                #pragma unroll
                for (int mi = 0; mi < 2; mi++){
                    int row = warp_m*32 + mi*16 + (lane & 15);
                    uint32_t off = (uint32_t)(row*128 + ks*32 + ((lane>>4)<<4));
                    ldm_x4(afr[mi], abuf + SWZ(off));
                }
                #pragma unroll
                for (int p = 0; p < 2; p++){
                    int row = warp_n*32 + p*16 + (lane & 15);
                    uint32_t off = (uint32_t)(row*128 + ks*32 + ((lane>>4)<<4));
                    ldm_x4(bfr[p], bbuf + SWZ(off));
                }
                #pragma unroll
                for (int mi = 0; mi < 2; mi++)
                    #pragma unroll
                    for (int ni = 0; ni < 4; ni++)
                        mma_bf16(acc[mi][ni], afr[mi],
                                 bfr[ni>>1][ni&1], bfr[ni>>1][2 + (ni&1)]);
            }
        }

        // write scores tile (scaled)
        #pragma unroll
        for (int ni = 0; ni < 4; ni++){
            int col = nt*128 + warp_n*32 + ni*8 + (lane & 3)*2;
            if (col >= KQ) continue;
            #pragma unroll
            for (int mi = 0; mi < 2; mi++){
                int rbase = warp_m*32 + mi*16 + (lane >> 2);
                #pragma unroll
                for (int h = 0; h < 2; h++){
                    int row = rbase + h*8;
                    scores[row*KQ + col]     = acc[mi][ni][h*2+0] * 0.0625f;
                    scores[row*KQ + col + 1] = acc[mi][ni][h*2+1] * 0.0625f;
                }
            }
        }
        __syncthreads();
    }

    // softmax: warp w handles rows w*8 .. w*8+7
    for (int rr = wid*8; rr < wid*8 + 8; rr++){
        int gq = m0 + rr;
        if (gq >= NQ) continue;
        float* srow = scores + rr*KQ;
        float m = -1e30f;
        for (int j = lane; j < NQ; j += 32) m = fmaxf(m, srow[j]);
        #pragma unroll
        for (int s = 16; s > 0; s >>= 1) m = fmaxf(m, __shfl_xor_sync(0xFFFFFFFF, m, s));
        float sum = 0.f;
        for (int j = lane; j < NQ; j += 32){ float e = expf(srow[j]-m); srow[j] = e; sum += e; }
        #pragma unroll
        for (int s = 16; s > 0; s >>= 1) sum += __shfl_xor_sync(0xFFFFFFFF, sum, s);
        float inv = 1.f / sum;
        bf16* orow = g_attn_bf + (long)(b*NQ + gq)*KQ;
        for (int j = lane; j < KQ; j += 32)
            orow[j] = __float2bfloat16(j < NQ ? srow[j]*inv : 0.f);
    }
}

// ===================================================================================
// Fused sampler: h1 = relu(q@w_r1^T+b), ro=tanh(h1@w_r2^T+b)*0.5, ref, bilinear sample.
// grid ROWS blocks, 256 threads.
// ===================================================================================
__global__ void __launch_bounds__(256) k_sampler(
    const float* __restrict__ w_r2, const float* __restrict__ b_r2,
    const float* __restrict__ b_r1)
{
    __shared__ float q_s[DM];
    __shared__ float h1_s[DM];
    __shared__ float ref_s[16];
    int r = blockIdx.x;
    int b = r / NQ;
    int tid = threadIdx.x;
    int lane = tid & 31, wid = tid >> 5;

    q_s[tid] = __bfloat162float(g_q_bf[(long)r*DM + tid]);
    __syncthreads();

    // h1
    float acc = b_r1[tid];
    #pragma unroll 8
    for (int k = 0; k < DM; k++)
        acc += q_s[k] * __bfloat162float(g_wr1T[(long)k*DM + tid]);
    h1_s[tid] = fmaxf(acc, 0.f);
    __syncthreads();

    // ref (16 outputs, 2 per warp)
    #pragma unroll
    for (int jj = 0; jj < 2; jj++){
        int j = wid*2 + jj;
        float part = 0.f;
        for (int k = lane; k < DM; k += 32)
            part += h1_s[k] * w_r2[j*DM + k];
        #pragma unroll
        for (int s = 16; s > 0; s >>= 1) part += __shfl_xor_sync(0xFFFFFFFF, part, s);
        if (lane == 0){
            float ro = tanhf(part + b_r2[j]) * 0.5f;
            int c = j & 1;
            float v = g_boxes[r*4 + c] + ro;
            ref_s[j] = fminf(fmaxf(v, 0.f), 1.f);
        }
    }
    __syncthreads();

    // sampling: p = point, cg = 8-channel group
    int p  = tid >> 5;
    int cg = tid & 31;
    int rp = r*NP + p;
    float rx = ref_s[p*2+0], ry = ref_s[p*2+1];
    const bf16* f1 = g_f1bf + (long)b*HW*DM;
    float gx0 = rx*2.f - 1.f;
    float gy0 = ry*2.f - 1.f;
    #pragma unroll
    for (int t=0;t<9;t++){
        float ox = (float)(t%3 - 1), oy = (float)(t/3 - 1);
        float gx = gx0 + ox*(2.f/WW);
        float gy = gy0 + oy*(2.f/HH);
        float x = fminf(fmaxf((gx+1.f)*0.5f*(WW-1), 0.f), (float)(WW-1));
        float y = fminf(fmaxf((gy+1.f)*0.5f*(HH-1), 0.f), (float)(HH-1));
        float x0f = floorf(x), y0f = floorf(y);
        float wx = x - x0f, wy = y - y0f;
        int x0 = (int)x0f, y0 = (int)y0f;
        int x1 = min(x0+1, WW-1), y1 = min(y0+1, HH-1);
        float w00 = (1.f-wx)*(1.f-wy), w01 = wx*(1.f-wy);
        float w10 = (1.f-wx)*wy,       w11 = wx*wy;
        uint4 q00 = *((const uint4*)(f1 + ((long)y0*WW + x0)*DM) + cg);
        uint4 q01 = *((const uint4*)(f1 + ((long)y0*WW + x1)*DM) + cg);
        uint4 q10 = *((const uint4*)(f1 + ((long)y1*WW + x0)*DM) + cg);
        uint4 q11 = *((const uint4*)(f1 + ((long)y1*WW + x1)*DM) + cg);
        const uint32_t* a00 = (const uint32_t*)&q00;
        const uint32_t* a01 = (const uint32_t*)&q01;
        const uint32_t* a10 = (const uint32_t*)&q10;
        const uint32_t* a11 = (const uint32_t*)&q11;
        uint4 o;
        uint32_t* o32 = (uint32_t*)&o;
        #pragma unroll
        for (int j = 0; j < 4; j++){
            float2 f00 = __bfloat1622float2(*(const __nv_bfloat162*)&a00[j]);
            float2 f01 = __bfloat1622float2(*(const __nv_bfloat162*)&a01[j]);
            float2 f10 = __bfloat1622float2(*(const __nv_bfloat162*)&a10[j]);
            float2 f11 = __bfloat1622float2(*(const __nv_bfloat162*)&a11[j]);
            float vx = f00.x*w00 + f01.x*w01 + f10.x*w10 + f11.x*w11;
            float vy = f00.y*w00 + f01.y*w01 + f10.y*w10 + f11.y*w11;
            __nv_bfloat162 pk = __floats2bfloat162_rn(vx, vy);
            o32[j] = *(uint32_t*)&pk;
        }
        *((uint4*)(g_sampled_bf + (long)rp*KP + t*DM) + cg) = o;
    }
}

// ===================================================================================
// Fused box head: hb = relu(q@w_b1^T+b_b1); delta = sigmoid(hb@w_b2^T+b_b2); box update.
// grid ROWS blocks, 256 threads.
// ===================================================================================
__global__ void __launch_bounds__(256) k_boxhead(
    const float* __restrict__ w_b2, const float* __restrict__ b_b2,
    const float* __restrict__ b_b1)
{
    __shared__ float q_s[DM];
    __shared__ float hb_s[DM];
    int r = blockIdx.x;
    int tid = threadIdx.x;
    int lane = tid & 31, wid = tid >> 5;

    q_s[tid] = __bfloat162float(g_q_bf[(long)r*DM + tid]);
    __syncthreads();

    float acc = b_b1[tid];
    #pragma unroll 8
    for (int k = 0; k < DM; k++)
        acc += q_s[k] * __bfloat162float(g_wb1T[(long)k*DM + tid]);
    hb_s[tid] = fmaxf(acc, 0.f);
    __syncthreads();

    if (wid < 4){
        int j = wid;
        float part = 0.f;
        for (int k = lane; k < DM; k += 32)
            part += hb_s[k] * w_b2[j*DM + k];
        #pragma unroll
        for (int s = 16; s > 0; s >>= 1) part += __shfl_xor_sync(0xFFFFFFFF, part, s);
        if (lane == 0){
            float delta = 1.f/(1.f + expf(-(part + b_b2[j])));
            float v = g_boxes[r*4 + j] + 0.1f*tanhf(delta - 0.5f);
            g_boxes[r*4 + j] = fminf(fmaxf(v, 0.f), 1.f);
        }
    }
}

// ----------------------------- small kernels -----------------------------
__global__ void k_cast(const float* __restrict__ s, bf16* __restrict__ d, int n){
    int i = blockIdx.x*256 + threadIdx.x;
    if (i < n) d[i] = __float2bfloat16(s[i]);
}

#define S1 (DM*DM)
__global__ void k_prep_small(const float* __restrict__ w_lat, const float* __restrict__ w_r1,
                             const float* __restrict__ w_b1, const float* __restrict__ Wq,
                             const float* __restrict__ Wo, const float* __restrict__ Wp2){
    int idx = blockIdx.x*256 + threadIdx.x;
    if (idx < S1){
        g_wlat_bf[idx] = __float2bfloat16(w_lat[idx]);
    } else if (idx < 2*S1){
        int i = idx - S1;
        int k = i / DM, o = i % DM;
        g_wr1T[i] = __float2bfloat16(w_r1[o*DM + k]);
    } else if (idx < 3*S1){
        int i = idx - 2*S1;
        int k = i / DM, o = i % DM;
        g_wb1T[i] = __float2bfloat16(w_b1[o*DM + k]);
    } else if (idx < (3+NL)*S1){
        int i = idx - 3*S1;
        g_Wq_bf[i] = __float2bfloat16(Wq[i]);
    } else if (idx < (3+2*NL)*S1){
        int i = idx - (3+NL)*S1;
        g_Wo_bf[i] = __float2bfloat16(Wo[i]);
    } else if (idx < (3+3*NL)*S1){
        int i = idx - (3+2*NL)*S1;
        g_Wp2_bf[i] = __float2bfloat16(Wp2[i]);
    }
}

__global__ void k_fuse_w(const float* __restrict__ w_tf, const float* __restrict__ b_tf,
                         const float* __restrict__ w_in, const float* __restrict__ b_in)
{
    int d = blockIdx.x;
    int t = threadIdx.x;   // 128
    __shared__ float win_s[CIN];
    __shared__ float red[CIN];
    win_s[t] = w_in[d*CIN + t];
    __syncthreads();
    int i = t;
    for (int kd=0; kd<3; kd++){
        float acc = 0.f;
        for (int o=0;o<CIN;o++) acc += win_s[o]*w_tf[(o*CIN + i)*3 + kd];
        g_Wf_bf[d*K3 + kd*CIN + i] = __float2bfloat16(acc * (1.0f/TT));
    }
    red[t] = win_s[t]*b_tf[t];
    __syncthreads();
    for (int s=64;s>0;s>>=1){ if (t<s) red[t]+=red[t+s]; __syncthreads(); }
    if (t==0) g_bfv[d] = b_in[d] + red[0];
}

__global__ void k_wsm_flat(const float* __restrict__ w_sm){
    int idx = blockIdx.x*256 + threadIdx.x;
    if (idx >= DM*KP) return;
    int o = idx / KP;
    int r = idx % KP;
    int t = r / DM, c = r % DM;
    g_wsm_bf[idx] = __float2bfloat16(w_sm[((long)o*DM + c)*9 + t]);
}

__global__ void k_tsum(const float* __restrict__ feat){
    int idx = blockIdx.x*256 + threadIdx.x;
    if (idx >= BB*CIN*HW) return;
    int p = idx % HW;
    int i = (idx/HW) % CIN;
    int b = idx/(HW*CIN);
    const float* f = feat + (((long)b*TT)*CIN + i)*HW + p;
    const long st = (long)CIN*HW;
    float v0=f[0], v1=f[st], v2=f[2*st], v3=f[3*st];
    float s = v0+v1+v2+v3;
    bf16* o = g_St + ((long)b*HW + p)*K3 + i;
    o[0*CIN] = __float2bfloat16(s - v3);
    o[1*CIN] = __float2bfloat16(s);
    o[2*CIN] = __float2bfloat16(s - v0);
}

__global__ void k_init(const float* __restrict__ q_embed, const float* __restrict__ q_pos,
                       const float* __restrict__ boxes0){
    int idx = blockIdx.x*256 + threadIdx.x;
    if (idx < ROWS*DM){
        int qd = idx % (NQ*DM);
        float v = q_embed[qd] + q_pos[qd];
        g_queries[idx] = v;
        g_q_bf[idx] = __float2bfloat16(v);
    }
    if (idx < ROWS*4) g_boxes[idx] = boxes0[idx];
    if (idx < BB*DM*KQ) g_kvt[idx] = __float2bfloat16(0.f);
}

__global__ void k_mean_p(){
    int idx = blockIdx.x*256 + threadIdx.x;
    if (idx >= ROWS*DM) return;
    int k = idx % DM;
    long r = idx / DM;
    const bf16* p = g_pv_bf + r*NP*DM + k;
    float s = 0.f;
    #pragma unroll
    for (int j=0;j<NP;j++) s += __bfloat162float(p[(long)j*DM]);
    g_pvm_bf[idx] = __float2bfloat16(s * (1.0f/NP));
}

__global__ void k_final(const float* __restrict__ w_cls, const float* __restrict__ b_cls,
                        float* __restrict__ out){
    int idx = blockIdx.x*256 + threadIdx.x;
    if (idx >= ROWS + ROWS*4) return;
    if (idx < ROWS){
        const float* q = g_queries + (long)idx*DM;
        float acc = 0.f;
        for (int k=0;k<DM;k++) acc += q[k]*w_cls[k];
        out[idx] = acc + b_cls[0];
    } else {
        out[idx] = g_boxes[idx - ROWS];
    }
}

// ----------------------------- launcher -----------------------------
static inline int ceil_div(int a, int b){ return (a+b-1)/b; }

extern "C" void kernel_launch(void* const* d_in, const int* in_sizes, int n_in,
                              void* d_out, int out_size)
{
    const float* feat    = (const float*)d_in[0];
    const float* boxes0  = (const float*)d_in[1];
    const float* w_tf    = (const float*)d_in[2];
    const float* b_tf    = (const float*)d_in[3];
    const float* w_in    = (const float*)d_in[4];
    const float* b_in    = (const float*)d_in[5];
    const float* w_lat   = (const float*)d_in[6];
    const float* b_lat   = (const float*)d_in[7];
    const float* w_sm    = (const float*)d_in[8];
    const float* b_sm    = (const float*)d_in[9];
    const float* q_embed = (const float*)d_in[10];
    const float* q_pos   = (const float*)d_in[11];
    const float* Wq      = (const float*)d_in[12];
    const float* bq      = (const float*)d_in[13];
    const float* Wo      = (const float*)d_in[14];
    const float* bo      = (const float*)d_in[15];
    const float* Wp1     = (const float*)d_in[16];
    const float* bp1     = (const float*)d_in[17];
    const float* Wp2     = (const float*)d_in[18];
    const float* bp2     = (const float*)d_in[19];
    const float* w_r1    = (const float*)d_in[20];
    const float* b_r1    = (const float*)d_in[21];
    const float* w_r2    = (const float*)d_in[22];
    const float* b_r2    = (const float*)d_in[23];
    const float* w_b1    = (const float*)d_in[24];
    const float* b_b1    = (const float*)d_in[25];
    const float* w_b2    = (const float*)d_in[26];
    const float* b_b2    = (const float*)d_in[27];
    const float* w_cls   = (const float*)d_in[28];
    const float* b_cls   = (const float*)d_in[29];
    float* out = (float*)d_out;

    cudaFuncSetAttribute(k_hmma, cudaFuncAttributeMaxDynamicSharedMemorySize, SMEM_DYN);
    cudaFuncSetAttribute(k_conv_hmma, cudaFuncAttributeMaxDynamicSharedMemorySize, SMEM_DYN);
    cudaFuncSetAttribute(k_attn, cudaFuncAttributeMaxDynamicSharedMemorySize, ATTN_SMEM);

    float *pbfv, *pq;
    bf16 *pSt, *pWfb, *pxbf, *platbf, *pf1bf, *pwsmb, *pwlatb;
    bf16 *pWqb, *pWob, *pWp2b, *pWp1b, *pqbf, *psamp, *ppvb, *ppvmb, *pkvb, *pkvt, *pqqb, *pattnb, *paob;
    cudaGetSymbolAddress((void**)&pSt,    g_St);
    cudaGetSymbolAddress((void**)&pWfb,   g_Wf_bf);
    cudaGetSymbolAddress((void**)&pbfv,   g_bfv);
    cudaGetSymbolAddress((void**)&pxbf,   g_xbf);
    cudaGetSymbolAddress((void**)&platbf, g_latbf);
    cudaGetSymbolAddress((void**)&pf1bf,  g_f1bf);
    cudaGetSymbolAddress((void**)&pwsmb,  g_wsm_bf);
    cudaGetSymbolAddress((void**)&pwlatb, g_wlat_bf);
    cudaGetSymbolAddress((void**)&pWqb,   g_Wq_bf);
    cudaGetSymbolAddress((void**)&pWob,   g_Wo_bf);
    cudaGetSymbolAddress((void**)&pWp2b,  g_Wp2_bf);
    cudaGetSymbolAddress((void**)&pWp1b,  g_Wp1_bf);
    cudaGetSymbolAddress((void**)&pq,     g_queries);
    cudaGetSymbolAddress((void**)&pqbf,   g_q_bf);
    cudaGetSymbolAddress((void**)&psamp,  g_sampled_bf);
    cudaGetSymbolAddress((void**)&ppvb,   g_pv_bf);
    cudaGetSymbolAddress((void**)&ppvmb,  g_pvm_bf);
    cudaGetSymbolAddress((void**)&pkvb,   g_kv_bf);
    cudaGetSymbolAddress((void**)&pkvt,   g_kvt);
    cudaGetSymbolAddress((void**)&pqqb,   g_qq_bf);
    cudaGetSymbolAddress((void**)&pattnb, g_attn_bf);
    cudaGetSymbolAddress((void**)&paob,   g_ao_bf);

    // ---------------- prologue ----------------
    k_fuse_w<<<DM, CIN>>>(w_tf, b_tf, w_in, b_in);
    k_wsm_flat<<<ceil_div(DM*KP,256), 256>>>(w_sm);
    k_prep_small<<<ceil_div((3+3*NL)*S1,256), 256>>>(w_lat, w_r1, w_b1, Wq, Wo, Wp2);
    k_cast<<<ceil_div(NL*DM*KP,256),256>>>(Wp1, pWp1b, NL*DM*KP);
    k_tsum<<<ceil_div(BB*CIN*HW,256), 256>>>(feat);

    // ---------------- backbone ----------------
    // x (+pos fused) -> bf16 channel-last
    k_hmma<<<dim3(HW/64, DM/128, BB), 256, SMEM_DYN>>>(
        pSt, pWfb, pbfv, nullptr, nullptr, pxbf, nullptr,
        HW, DM, K3, K3, K3, DM,
        (long)HW*K3, 0, (long)HW*DM, 0, 1.0f, 1);

    k_hmma<<<dim3(HW/64, DM/128, BB), 256, SMEM_DYN>>>(
        pxbf, pwlatb, b_lat, nullptr, nullptr, platbf, nullptr,
        HW, DM, DM, DM, DM, DM,
        (long)HW*DM, 0, (long)HW*DM, 0, 1.0f, 0);

    k_conv_hmma<<<dim3(BB*HW/64, DM/128), 256, SMEM_DYN>>>(platbf, pwsmb, b_sm, pf1bf);

    k_init<<<ceil_div(BB*DM*KQ,256), 256>>>(q_embed, q_pos, boxes0);

    // ---------------- decoder ----------------
    for (int l=0; l<NL; l++){
        const float* bq_l  = bq  + (long)l*DM;
        const float* bo_l  = bo  + (long)l*DM;
        const float* bp1_l = bp1 + (long)l*DM;
        const float* bp2_l = bp2 + (long)l*DM;
        bf16* Wq_l  = pWqb  + (long)l*DM*DM;
        bf16* Wo_l  = pWob  + (long)l*DM*DM;
        bf16* Wp2_l = pWp2b + (long)l*DM*DM;
        bf16* Wp1_l = pWp1b + (long)l*DM*KP;

        // qq = q_bf @ Wq^T + bq -> bf16
        k_hmma<<<dim3(ceil_div(ROWS,64), DM/128, 1), 256, SMEM_DYN>>>(
            pqbf, Wq_l, bq_l, nullptr, nullptr, pqqb, nullptr,
            ROWS, DM, DM, DM, DM, DM, 0,0,0, 0, 1.0f, 0);

        // fused h1 + ref + sample
        k_sampler<<<ROWS, 256>>>(w_r2, b_r2, b_r1);

        // pv = relu(sampled @ Wp1^T + bp1) -> bf16
        k_hmma<<<dim3(RP/64, DM/128, 1), 256, SMEM_DYN>>>(
            psamp, Wp1_l, bp1_l, nullptr, nullptr, ppvb, nullptr,
            RP, DM, KP, KP, KP, DM, 0,0,0, 1, 1.0f, 0);

        k_mean_p<<<ceil_div(ROWS*DM,256), 256>>>();

        // kv = pvm @ Wp2^T + bp2 -> bf16 (+ transposed)
        k_hmma<<<dim3(ceil_div(ROWS,64), DM/128, 1), 256, SMEM_DYN>>>(
            ppvmb, Wp2_l, bp2_l, nullptr, nullptr, pkvb, pkvt,
            ROWS, DM, DM, DM, DM, DM, 0,0,0, 0, 1.0f, 0);

        // fused logits + softmax -> attn_bf
        k_attn<<<dim3(ceil_div(NQ,64), 1, BB), 256, ATTN_SMEM>>>();

        // att_out[b] = attn_bf[b] @ kvt[b]^T -> bf16
        k_hmma<<<dim3(ceil_div(NQ,64), DM/128, BB), 256, SMEM_DYN>>>(
            pattnb, pkvt, nullptr, nullptr, nullptr, paob, nullptr,
            NQ, DM, KQ, KQ, KQ, DM,
            (long)NQ*KQ, (long)DM*KQ, (long)NQ*DM, 0, 1.0f, 0);

        // queries += att_out @ Wo^T + bo  (fp32 residual, dual-write bf16)
        k_hmma<<<dim3(ceil_div(ROWS,64), DM/128, 1), 256, SMEM_DYN>>>(
            paob, Wo_l, bo_l, pq, pq, pqbf, nullptr,
            ROWS, DM, DM, DM, DM, DM, 0,0,0, 0, 1.0f, 0);

        // fused hb + box update
        k_boxhead<<<ROWS, 256>>>(w_b2, b_b2, b_b1);
    }

    k_final<<<ceil_div(ROWS*5,256), 256>>>(w_cls, b_cls, out);
}